// round 13
// baseline (speedup 1.0000x reference)
#include <cuda_runtime.h>
#include <cuda_fp16.h>
#include <math.h>

#define NN 6000
#define EE 100000

// ---------------- device scratch (static, no allocation) ----------------
__device__ int g_deg[NN];          // zeroed at end of scan_kernel each launch (starts zeroed)
__device__ int g_rowptr[NN + 1];
__device__ int g_rank[EE];
__device__ int g_es[EE];           // packed per CSR slot: e | (src<<17) | (type<<30)

__device__ __align__(16) __half g_W0h[2 * NN * 32];  // layer-0 relation weights, fp16
__device__ __align__(16) float g_Wl1[2 * 32 * 64];
__device__ __align__(16) float g_Wl2[2 * 64 * 64];
__device__ __align__(16) float g_Wl3[2 * 64 * 32];
__device__ __align__(16) float g_hrA[2 * NN * 64];
__device__ __align__(16) float g_hrB[2 * NN * 64];
__device__ __align__(16) float g_rootout[NN * 64];
__device__ __align__(16) float g_rootout3[NN * 32];
__device__ __align__(16) __half g_hh[NN * 512];      // GAT hidden (fp16)
__device__ float g_asv[NN], g_adv[NN];
__device__ __align__(16) __half g_x16[NN * 512];     // GAT output features (fp16, GEMM A)
__device__ __align__(16) __half g_w1hT[256 * 512];   // w1 fp16, transposed [out][k]
__device__ __align__(16) __half g_pt16[NN * 128];    // x @ w1[0:512] (+ b1), fp16
__device__ __align__(16) __half g_pb16[NN * 128];    // x @ w1[512:1024], fp16

__device__ __forceinline__ float lrelu(float v) { return v > 0.f ? v : 0.2f * v; }

// load 4 consecutive halves as float4
__device__ __forceinline__ float4 ldh4(const uint2* base, size_t idx) {
    uint2 u = base[idx];
    __half2 p0 = *reinterpret_cast<__half2*>(&u.x);
    __half2 p1 = *reinterpret_cast<__half2*>(&u.y);
    float2 f0 = __half22float2(p0);
    float2 f1 = __half22float2(p1);
    return make_float4(f0.x, f0.y, f1.x, f1.y);
}

// ---------------- kernel 1: relation-weight precompute + degree count + w1->fp16T ----------------
#define W0_CNT (2 * NN * 32)
#define WL1_CNT (2 * 32 * 64)
#define WL2_CNT (2 * 64 * 64)
#define WL3_CNT (2 * 64 * 32)
#define PRE_CNT (W0_CNT + WL1_CNT + WL2_CNT + WL3_CNT)
#define PRE_BLOCKS (PRE_CNT / 256)              // exact
#define CNT_BLOCKS ((EE + 255) / 256)
#define W1H_BLOCKS ((256 * 512) / 256)          // 512

__global__ void pre_count_kernel(const float* __restrict__ basis0, const float* __restrict__ comp0,
                                 const float* __restrict__ basis1, const float* __restrict__ comp1,
                                 const float* __restrict__ basis2, const float* __restrict__ comp2,
                                 const float* __restrict__ basis3, const float* __restrict__ comp3,
                                 const int* __restrict__ dst, const float* __restrict__ w1) {
    int bid = blockIdx.x;
    if (bid >= PRE_BLOCKS + CNT_BLOCKS) {
        // w1 -> fp16 transposed: g_w1hT[o][i] = w1[(i + (o>=128?512:0))*128 + (o&127)]
        int idx = (bid - PRE_BLOCKS - CNT_BLOCKS) * 256 + threadIdx.x;
        int o = idx >> 9, i = idx & 511;
        g_w1hT[o * 512 + i] = __float2half(w1[(i + ((o >= 128) ? 512 : 0)) * 128 + (o & 127)]);
        return;
    }
    if (bid >= PRE_BLOCKS) {
        int e = (bid - PRE_BLOCKS) * 256 + threadIdx.x;
        if (e < EE) g_rank[e] = atomicAdd(&g_deg[dst[e]], 1);
        return;
    }
    int idx = bid * 256 + threadIdx.x;
    if (idx < W0_CNT) {
        int per = NN * 32;
        int r = idx / per, rem = idx - r * per;
        float v = 0.f;
#pragma unroll
        for (int b = 0; b < 4; b++) v += comp0[r * 4 + b] * basis0[b * per + rem];
        g_W0h[idx] = __float2half(v);
        return;
    }
    idx -= W0_CNT;
    if (idx < WL1_CNT) {
        int per = 32 * 64;
        int r = idx / per, rem = idx - r * per;
        float v = 0.f;
#pragma unroll
        for (int b = 0; b < 4; b++) v += comp1[r * 4 + b] * basis1[b * per + rem];
        g_Wl1[idx] = v;
        return;
    }
    idx -= WL1_CNT;
    if (idx < WL2_CNT) {
        int per = 64 * 64;
        int r = idx / per, rem = idx - r * per;
        float v = 0.f;
#pragma unroll
        for (int b = 0; b < 4; b++) v += comp2[r * 4 + b] * basis2[b * per + rem];
        g_Wl2[idx] = v;
        return;
    }
    idx -= WL2_CNT;
    {
        int per = 64 * 32;
        int r = idx / per, rem = idx - r * per;
        float v = 0.f;
#pragma unroll
        for (int b = 0; b < 4; b++) v += comp3[r * 4 + b] * basis3[b * per + rem];
        g_Wl3[idx] = v;
    }
}

// ---------------- kernel 2: single-pass scan (also re-zeroes deg for next launch) ----------------
__global__ void scan_kernel() {
    __shared__ int swsum[32];
    int tid = threadIdx.x, lane = tid & 31, wid = tid >> 5;
    int base = tid * 6;
    int v[6];
    int s = 0;
#pragma unroll
    for (int j = 0; j < 6; j++) {
        int i = base + j;
        v[j] = (i < NN) ? g_deg[i] : 0;
        s += v[j];
    }
    int x = s;
#pragma unroll
    for (int off = 1; off < 32; off <<= 1) {
        int t = __shfl_up_sync(0xffffffffu, x, off);
        if (lane >= off) x += t;
    }
    if (lane == 31) swsum[wid] = x;
    __syncthreads();
    if (wid == 0) {
        int y = swsum[lane];
#pragma unroll
        for (int off = 1; off < 32; off <<= 1) {
            int t = __shfl_up_sync(0xffffffffu, y, off);
            if (lane >= off) y += t;
        }
        swsum[lane] = y;
    }
    __syncthreads();
    int run = x - s + (wid ? swsum[wid - 1] : 0);
#pragma unroll
    for (int j = 0; j < 6; j++) {
        int i = base + j;
        run += v[j];
        if (i < NN) g_rowptr[i + 1] = run;
    }
    if (tid == 0) g_rowptr[0] = 0;
#pragma unroll
    for (int j = 0; j < 6; j++) {
        int i = base + j;
        if (i < NN) g_deg[i] = 0;   // restore invariant for next launch
    }
}

// ---------------- kernel 3: atomic-free scatter, packed slot ----------------
__global__ void scatter_kernel(const int* __restrict__ src, const int* __restrict__ dst,
                               const int* __restrict__ et) {
    int e = blockIdx.x * blockDim.x + threadIdx.x;
    if (e < EE) {
        int p = g_rowptr[dst[e]] + g_rank[e];
        g_es[p] = e | (src[e] << 17) | (et[e] << 30);
    }
}

#define ES_S(v) (((v) >> 17) & 0x1FFF)
#define ES_T(v) (((v) >> 30) & 1)
#define ES_E(v) ((v) & 0x1FFFF)

// ---------------- kernel 4: layer-0 agg (dual-edge half-warps, fp16 W0) + dense1 fused ----------
// 256 threads = 8 warps, 1 warp/node. Lanes 0-15 take even CSR slots, 16-31 odd;
// each lane covers 2 columns via __half2. Combine halves with one shfl_xor(16).
__global__ void l0d1_kernel(const float* __restrict__ root0, const float* __restrict__ rbias0,
                            const float* __restrict__ root1, const float* __restrict__ rbias1) {
    __shared__ float sx[8][32];
    int tid = threadIdx.x, w = tid >> 5, lane = tid & 31;
    int hl = lane & 15, side = lane >> 4;
    int node = blockIdx.x * 8 + w;
    {
        int beg = g_rowptr[node], end = g_rowptr[node + 1];
        float2 A0 = make_float2(0.f, 0.f), A1 = make_float2(0.f, 0.f);
        float C0 = 0.f, C1 = 0.f;
        int k = beg + side;
        // 2 edges in flight per lane (MLP 4 per warp)
        for (; k + 2 < end; k += 4) {
            int v0 = g_es[k], v1 = g_es[k + 2];
            float2 f0 = __half22float2(*(const __half2*)(g_W0h + ES_T(v0) * (NN * 32) + ES_S(v0) * 32 + 2 * hl));
            float2 f1 = __half22float2(*(const __half2*)(g_W0h + ES_T(v1) * (NN * 32) + ES_S(v1) * 32 + 2 * hl));
            if (ES_T(v0)) { A1.x += f0.x; A1.y += f0.y; C1 += 1.f; }
            else          { A0.x += f0.x; A0.y += f0.y; C0 += 1.f; }
            if (ES_T(v1)) { A1.x += f1.x; A1.y += f1.y; C1 += 1.f; }
            else          { A0.x += f1.x; A0.y += f1.y; C0 += 1.f; }
        }
        if (k < end) {
            int v = g_es[k];
            float2 f = __half22float2(*(const __half2*)(g_W0h + ES_T(v) * (NN * 32) + ES_S(v) * 32 + 2 * hl));
            if (ES_T(v)) { A1.x += f.x; A1.y += f.y; C1 += 1.f; }
            else         { A0.x += f.x; A0.y += f.y; C0 += 1.f; }
        }
        // combine even/odd halves
        A0.x += __shfl_xor_sync(0xffffffffu, A0.x, 16);
        A0.y += __shfl_xor_sync(0xffffffffu, A0.y, 16);
        A1.x += __shfl_xor_sync(0xffffffffu, A1.x, 16);
        A1.y += __shfl_xor_sync(0xffffffffu, A1.y, 16);
        C0 += __shfl_xor_sync(0xffffffffu, C0, 16);
        C1 += __shfl_xor_sync(0xffffffffu, C1, 16);
        if (side == 0) {
            int col = hl * 2;
            float i0 = 1.f / fmaxf(C0, 1.f), i1 = 1.f / fmaxf(C1, 1.f);
            float o0 = root0[node * 32 + col] + rbias0[col] + A0.x * i0 + A1.x * i1;
            float o1 = root0[node * 32 + col + 1] + rbias0[col + 1] + A0.y * i0 + A1.y * i1;
            sx[w][col] = tanhf(o0);
            sx[w][col + 1] = tanhf(o1);
        }
    }
    __syncthreads();
    // dense1: 8 nodes x 64 outputs = 512 outputs, 2 per thread
#pragma unroll
    for (int t = tid; t < 512; t += 256) {
        int ln = t >> 6, o = t & 63;
        int nn = blockIdx.x * 8 + ln;
        float a0 = 0.f, a1 = 0.f, ar = 0.f;
#pragma unroll 8
        for (int i = 0; i < 32; i++) {
            float xv = sx[ln][i];
            a0 += xv * g_Wl1[i * 64 + o];
            a1 += xv * g_Wl1[32 * 64 + i * 64 + o];
            ar += xv * root1[i * 64 + o];
        }
        g_hrA[nn * 64 + o] = a0;
        g_hrA[NN * 64 + nn * 64 + o] = a1;
        g_rootout[nn * 64 + o] = ar + rbias1[o];
    }
}

// ---------------- kernel 5: agg1 + dense2 fused ----------------
__global__ void a1d2_kernel(const float* __restrict__ root2, const float* __restrict__ rbias2) {
    __shared__ float sx[4][64];
    int tid = threadIdx.x;
    int ln = tid >> 6, o = tid & 63;
    int node = blockIdx.x * 4 + ln;
    {
        int beg = g_rowptr[node], end = g_rowptr[node + 1];
        float a0 = 0.f, a1 = 0.f, c0 = 0.f, c1 = 0.f;
        int k = beg;
        for (; k + 4 <= end; k += 4) {
            int v0 = g_es[k], v1 = g_es[k + 1], v2 = g_es[k + 2], v3 = g_es[k + 3];
            float f0 = g_hrA[ES_T(v0) * (NN * 64) + ES_S(v0) * 64 + o];
            float f1 = g_hrA[ES_T(v1) * (NN * 64) + ES_S(v1) * 64 + o];
            float f2 = g_hrA[ES_T(v2) * (NN * 64) + ES_S(v2) * 64 + o];
            float f3 = g_hrA[ES_T(v3) * (NN * 64) + ES_S(v3) * 64 + o];
            if (ES_T(v0)) { a1 += f0; c1 += 1.f; } else { a0 += f0; c0 += 1.f; }
            if (ES_T(v1)) { a1 += f1; c1 += 1.f; } else { a0 += f1; c0 += 1.f; }
            if (ES_T(v2)) { a1 += f2; c1 += 1.f; } else { a0 += f2; c0 += 1.f; }
            if (ES_T(v3)) { a1 += f3; c1 += 1.f; } else { a0 += f3; c0 += 1.f; }
        }
        for (; k < end; k++) {
            int v = g_es[k];
            float f = g_hrA[ES_T(v) * (NN * 64) + ES_S(v) * 64 + o];
            if (ES_T(v)) { a1 += f; c1 += 1.f; } else { a0 += f; c0 += 1.f; }
        }
        float out = g_rootout[node * 64 + o] + a0 / fmaxf(c0, 1.f) + a1 / fmaxf(c1, 1.f);
        sx[ln][o] = tanhf(out);
    }
    __syncthreads();
    float a0 = 0.f, a1 = 0.f, ar = 0.f;
#pragma unroll 8
    for (int i = 0; i < 64; i++) {
        float xv = sx[ln][i];
        a0 += xv * g_Wl2[i * 64 + o];
        a1 += xv * g_Wl2[64 * 64 + i * 64 + o];
        ar += xv * root2[i * 64 + o];
    }
    g_hrB[node * 64 + o] = a0;
    g_hrB[NN * 64 + node * 64 + o] = a1;
    g_rootout[node * 64 + o] = ar + rbias2[o];
}

// ---------------- kernel 6: agg2 + dense3 fused ----------------
__global__ void a2d3_kernel(const float* __restrict__ root3, const float* __restrict__ rbias3) {
    __shared__ float sx[4][64];
    int tid = threadIdx.x;
    int ln = tid >> 6, o = tid & 63;
    int node = blockIdx.x * 4 + ln;
    {
        int beg = g_rowptr[node], end = g_rowptr[node + 1];
        float a0 = 0.f, a1 = 0.f, c0 = 0.f, c1 = 0.f;
        int k = beg;
        for (; k + 4 <= end; k += 4) {
            int v0 = g_es[k], v1 = g_es[k + 1], v2 = g_es[k + 2], v3 = g_es[k + 3];
            float f0 = g_hrB[ES_T(v0) * (NN * 64) + ES_S(v0) * 64 + o];
            float f1 = g_hrB[ES_T(v1) * (NN * 64) + ES_S(v1) * 64 + o];
            float f2 = g_hrB[ES_T(v2) * (NN * 64) + ES_S(v2) * 64 + o];
            float f3 = g_hrB[ES_T(v3) * (NN * 64) + ES_S(v3) * 64 + o];
            if (ES_T(v0)) { a1 += f0; c1 += 1.f; } else { a0 += f0; c0 += 1.f; }
            if (ES_T(v1)) { a1 += f1; c1 += 1.f; } else { a0 += f1; c0 += 1.f; }
            if (ES_T(v2)) { a1 += f2; c1 += 1.f; } else { a0 += f2; c0 += 1.f; }
            if (ES_T(v3)) { a1 += f3; c1 += 1.f; } else { a0 += f3; c0 += 1.f; }
        }
        for (; k < end; k++) {
            int v = g_es[k];
            float f = g_hrB[ES_T(v) * (NN * 64) + ES_S(v) * 64 + o];
            if (ES_T(v)) { a1 += f; c1 += 1.f; } else { a0 += f; c0 += 1.f; }
        }
        float out = g_rootout[node * 64 + o] + a0 / fmaxf(c0, 1.f) + a1 / fmaxf(c1, 1.f);
        sx[ln][o] = tanhf(out);
    }
    __syncthreads();
    if (tid < 128) {
        int ln3 = tid >> 5, o3 = tid & 31;
        int nn = blockIdx.x * 4 + ln3;
        float a0 = 0.f, a1 = 0.f, ar = 0.f;
#pragma unroll 8
        for (int i = 0; i < 64; i++) {
            float xv = sx[ln3][i];
            a0 += xv * g_Wl3[i * 32 + o3];
            a1 += xv * g_Wl3[64 * 32 + i * 32 + o3];
            ar += xv * root3[i * 32 + o3];
        }
        g_hrA[nn * 32 + o3] = a0;
        g_hrA[NN * 32 + nn * 32 + o3] = a1;
        g_rootout3[nn * 32 + o3] = ar + rbias3[o3];
    }
}

// ---------------- kernel 7: agg3 + GAT h GEMM + asv/adv, fused (h stored fp16) ----------------
__global__ void agg3_gath_kernel(const float* __restrict__ gw,
                                 const float* __restrict__ as, const float* __restrict__ ad) {
    __shared__ __align__(16) float sx[16][32];
    __shared__ float s_as[16], s_ad[16];
    int tid = threadIdx.x;  // 512
    int node0 = blockIdx.x * 16;
    int w = tid >> 5, lane = tid & 31;
    // phase 0: agg3, warp per node
    {
        int node = node0 + w;
        int beg = g_rowptr[node], end = g_rowptr[node + 1];
        float a0 = 0.f, a1 = 0.f, c0 = 0.f, c1 = 0.f;
        int k = beg;
        for (; k + 4 <= end; k += 4) {
            int v0 = g_es[k], v1 = g_es[k + 1], v2 = g_es[k + 2], v3 = g_es[k + 3];
            float f0 = g_hrA[ES_T(v0) * (NN * 32) + ES_S(v0) * 32 + lane];
            float f1 = g_hrA[ES_T(v1) * (NN * 32) + ES_S(v1) * 32 + lane];
            float f2 = g_hrA[ES_T(v2) * (NN * 32) + ES_S(v2) * 32 + lane];
            float f3 = g_hrA[ES_T(v3) * (NN * 32) + ES_S(v3) * 32 + lane];
            if (ES_T(v0)) { a1 += f0; c1 += 1.f; } else { a0 += f0; c0 += 1.f; }
            if (ES_T(v1)) { a1 += f1; c1 += 1.f; } else { a0 += f1; c0 += 1.f; }
            if (ES_T(v2)) { a1 += f2; c1 += 1.f; } else { a0 += f2; c0 += 1.f; }
            if (ES_T(v3)) { a1 += f3; c1 += 1.f; } else { a0 += f3; c0 += 1.f; }
        }
        for (; k < end; k++) {
            int v = g_es[k];
            float f = g_hrA[ES_T(v) * (NN * 32) + ES_S(v) * 32 + lane];
            if (ES_T(v)) { a1 += f; c1 += 1.f; } else { a0 += f; c0 += 1.f; }
        }
        float out = g_rootout3[node * 32 + lane] + a0 / fmaxf(c0, 1.f) + a1 / fmaxf(c1, 1.f);
        sx[w][lane] = tanhf(out);
    }
    if (tid < 16) { s_as[tid] = 0.f; s_ad[tid] = 0.f; }
    __syncthreads();
    // phase 1: GEMM 32 -> 512 with fused attention-logit dots
    int cg = tid & 127;
    int ng = tid >> 7;
    int col4 = cg * 4;
    int nbase = ng * 4;
    float acc[4][4];
#pragma unroll
    for (int a = 0; a < 4; a++)
#pragma unroll
        for (int b = 0; b < 4; b++) acc[a][b] = 0.f;
#pragma unroll 8
    for (int i = 0; i < 32; i++) {
        float4 wv = *(const float4*)(gw + i * 512 + col4);
        float x0 = sx[nbase + 0][i], x1 = sx[nbase + 1][i];
        float x2 = sx[nbase + 2][i], x3 = sx[nbase + 3][i];
        acc[0][0] += x0 * wv.x; acc[0][1] += x0 * wv.y; acc[0][2] += x0 * wv.z; acc[0][3] += x0 * wv.w;
        acc[1][0] += x1 * wv.x; acc[1][1] += x1 * wv.y; acc[1][2] += x1 * wv.z; acc[1][3] += x1 * wv.w;
        acc[2][0] += x2 * wv.x; acc[2][1] += x2 * wv.y; acc[2][2] += x2 * wv.z; acc[2][3] += x2 * wv.w;
        acc[3][0] += x3 * wv.x; acc[3][1] += x3 * wv.y; acc[3][2] += x3 * wv.z; acc[3][3] += x3 * wv.w;
    }
#pragma unroll
    for (int a = 0; a < 4; a++) {
        int nn = node0 + nbase + a;
        __half2 h0 = __floats2half2_rn(acc[a][0], acc[a][1]);
        __half2 h1 = __floats2half2_rn(acc[a][2], acc[a][3]);
        uint2 u;
        u.x = *reinterpret_cast<unsigned*>(&h0);
        u.y = *reinterpret_cast<unsigned*>(&h1);
        *reinterpret_cast<uint2*>(g_hh + (size_t)nn * 512 + col4) = u;
    }
    float4 av = *(const float4*)(as + col4);
    float4 dv = *(const float4*)(ad + col4);
#pragma unroll
    for (int a = 0; a < 4; a++) {
        float ps = acc[a][0] * av.x + acc[a][1] * av.y + acc[a][2] * av.z + acc[a][3] * av.w;
        float pd = acc[a][0] * dv.x + acc[a][1] * dv.y + acc[a][2] * dv.z + acc[a][3] * dv.w;
#pragma unroll
        for (int off = 16; off; off >>= 1) {
            ps += __shfl_down_sync(0xffffffffu, ps, off);
            pd += __shfl_down_sync(0xffffffffu, pd, off);
        }
        if (lane == 0) {
            atomicAdd(&s_as[nbase + a], ps);
            atomicAdd(&s_ad[nbase + a], pd);
        }
    }
    __syncthreads();
    if (tid < 16) {
        int nn = node0 + tid;
        g_asv[nn] = s_as[tid];
        g_adv[nn] = s_ad[tid];
    }
}

// ---------------- kernel 8: GAT softmax-agg -> fp16 node features ----------------
// 16 nodes/block, 256 threads = 2 groups of 128 (named barriers 1/2). No GEMM here.
__global__ void gatagg_kernel(const float* __restrict__ gbias) {
    __shared__ float sex[2][64];
    __shared__ int ssrc[2][64];
    int tid = threadIdx.x;
    int node0 = blockIdx.x * 16;
    int g = tid >> 7;
    int gtid = tid & 127;
    const uint2* h2 = (const uint2*)g_hh;   // 4 halves per uint2
    float4 gb4 = ((const float4*)gbias)[gtid];
    for (int k = 0; k < 8; k++) {
        int n = node0 + g * 8 + k;
        int beg = g_rowptr[n], deg = g_rowptr[n + 1] - beg;
        float advn = g_adv[n];
        float exself = expf(lrelu(g_asv[n] + advn));
        float4 hs = ldh4(h2, (size_t)n * 128 + gtid);
        float ax = exself * hs.x, ay = exself * hs.y, az = exself * hs.z, aw = exself * hs.w;
        float dsum = exself;
        for (int base = 0; base < deg; base += 64) {
            int cnt = min(64, deg - base);
            if (gtid < cnt) {
                int v = g_es[beg + base + gtid];
                int s = ES_S(v);
                ssrc[g][gtid] = s;
                sex[g][gtid] = expf(lrelu(g_asv[s] + advn));
            }
            asm volatile("bar.sync %0, %1;" :: "r"(g + 1), "r"(128) : "memory");
            for (int j = 0; j < cnt; j++) {
                float exv = sex[g][j];
                float4 hv = ldh4(h2, (size_t)ssrc[g][j] * 128 + gtid);
                ax += exv * hv.x; ay += exv * hv.y; az += exv * hv.z; aw += exv * hv.w;
                dsum += exv;
            }
            asm volatile("bar.sync %0, %1;" :: "r"(g + 1), "r"(128) : "memory");
        }
        float inv = 1.f / fmaxf(dsum, 1e-16f);
        float ox = fmaxf(ax * inv + gb4.x, 0.f);
        float oy = fmaxf(ay * inv + gb4.y, 0.f);
        float oz = fmaxf(az * inv + gb4.z, 0.f);
        float ow = fmaxf(aw * inv + gb4.w, 0.f);
        __half2 p0 = __floats2half2_rn(ox, oy);
        __half2 p1 = __floats2half2_rn(oz, ow);
        uint2 u;
        u.x = *reinterpret_cast<unsigned*>(&p0);
        u.y = *reinterpret_cast<unsigned*>(&p1);
        *reinterpret_cast<uint2*>(g_x16 + (size_t)n * 512 + gtid * 4) = u;
    }
}

// ---------------- kernel 9: pt/pb GEMM via tensor cores (m16n8k16 fp16/fp32) ----------------
// grid (188, 2): blockIdx.x = 32-node tile, blockIdx.y = 128-col half.
// 256 threads = 8 warps: warp tile 16(m) x 32(n). K=512 streamed in 64-chunks.
#define MT 32
__global__ void ptpb_mma_kernel(const float* __restrict__ b1) {
    __shared__ __align__(16) __half As[MT][72];
    __shared__ __align__(16) __half Bs[128][72];
    int tid = threadIdx.x;
    int node0 = blockIdx.x * MT;
    int nblk = blockIdx.y;
    int w = tid >> 5, lane = tid & 31;
    int wm = (w >> 2) * 16;
    int wn = (w & 3) * 32;
    int grp = lane >> 2, tig = lane & 3;
    float acc[4][4];
#pragma unroll
    for (int a = 0; a < 4; a++)
#pragma unroll
        for (int b = 0; b < 4; b++) acc[a][b] = 0.f;
    const __half* wT = g_w1hT + (size_t)nblk * 128 * 512;
#pragma unroll 1
    for (int kt = 0; kt < 8; kt++) {
        int k0 = kt * 64;
        // load A: 32 nodes x 64 k; thread -> 8 halves
        {
            int m = tid >> 3, kc = (tid & 7) * 8;
            int node = node0 + m;
            uint4 v = make_uint4(0u, 0u, 0u, 0u);
            if (node < NN) v = *(const uint4*)(g_x16 + (size_t)node * 512 + k0 + kc);
            *(uint4*)&As[m][kc] = v;
        }
        // load B: 128 cols x 64 k; thread -> 32 halves
        {
            int n = tid >> 1, kc = (tid & 1) * 32;
            const __half* src = wT + (size_t)n * 512 + k0 + kc;
            uint4 v0 = ((const uint4*)src)[0];
            uint4 v1 = ((const uint4*)src)[1];
            uint4 v2 = ((const uint4*)src)[2];
            uint4 v3 = ((const uint4*)src)[3];
            *(uint4*)&Bs[n][kc] = v0;
            *(uint4*)&Bs[n][kc + 8] = v1;
            *(uint4*)&Bs[n][kc + 16] = v2;
            *(uint4*)&Bs[n][kc + 24] = v3;
        }
        __syncthreads();
#pragma unroll
        for (int ks = 0; ks < 4; ks++) {
            int kk = ks * 16 + tig * 2;
            unsigned a0 = *(const unsigned*)&As[wm + grp][kk];
            unsigned a1 = *(const unsigned*)&As[wm + grp + 8][kk];
            unsigned a2 = *(const unsigned*)&As[wm + grp][kk + 8];
            unsigned a3 = *(const unsigned*)&As[wm + grp + 8][kk + 8];
#pragma unroll
            for (int nf = 0; nf < 4; nf++) {
                int n8 = wn + nf * 8 + grp;
                unsigned b0 = *(const unsigned*)&Bs[n8][kk];
                unsigned b1r = *(const unsigned*)&Bs[n8][kk + 8];
                asm volatile(
                    "mma.sync.aligned.m16n8k16.row.col.f32.f16.f16.f32 "
                    "{%0,%1,%2,%3}, {%4,%5,%6,%7}, {%8,%9}, {%0,%1,%2,%3};"
                    : "+f"(acc[nf][0]), "+f"(acc[nf][1]), "+f"(acc[nf][2]), "+f"(acc[nf][3])
                    : "r"(a0), "r"(a1), "r"(a2), "r"(a3), "r"(b0), "r"(b1r));
            }
        }
        __syncthreads();
    }
    // epilogue: fp16 outputs. c0/c1 -> (row grp, cols tig*2, tig*2+1); c2/c3 -> row grp+8
#pragma unroll
    for (int nf = 0; nf < 4; nf++) {
        int ncol = nblk * 128 + wn + nf * 8 + tig * 2;   // global col 0..255
        float bx_ = 0.f, by_ = 0.f;
        __half* obase;
        int oc;
        if (ncol < 128) {
            obase = g_pt16; oc = ncol;
            float2 bb = *(const float2*)(b1 + ncol);
            bx_ = bb.x; by_ = bb.y;
        } else {
            obase = g_pb16; oc = ncol - 128;
        }
        int n0 = node0 + wm + grp;
        if (n0 < NN)
            *(__half2*)(obase + (size_t)n0 * 128 + oc) =
                __floats2half2_rn(acc[nf][0] + bx_, acc[nf][1] + by_);
        int n1 = n0 + 8;
        if (n1 < NN)
            *(__half2*)(obase + (size_t)n1 * 128 + oc) =
                __floats2half2_rn(acc[nf][2] + bx_, acc[nf][3] + by_);
    }
}

// ---------------- kernel 10: per-edge output, CSR order (pb[dst] loaded once/warp) ----------------
__global__ void edge_out_kernel(const float* __restrict__ w2, const float* __restrict__ b2,
                                float* __restrict__ out) {
    int tid = threadIdx.x, w = tid >> 5, lane = tid & 31;
    int node = blockIdx.x * 8 + w;
    int beg = g_rowptr[node], end = g_rowptr[node + 1];
    if (beg == end) return;
    const uint2* pt2 = (const uint2*)g_pt16;   // 4 halves per uint2; 32 per row
    const uint2* pb2 = (const uint2*)g_pb16;
    float4 pbv = ldh4(pb2, (size_t)node * 32 + lane);
    float4 wv = ((const float4*)w2)[lane];
    float bias = b2[0];
    int k = beg;
    for (; k + 2 <= end; k += 2) {
        int v0 = g_es[k], v1 = g_es[k + 1];
        float4 a0 = ldh4(pt2, (size_t)ES_S(v0) * 32 + lane);
        float4 a1 = ldh4(pt2, (size_t)ES_S(v1) * 32 + lane);
        float r0 = fmaxf(a0.x + pbv.x, 0.f) * wv.x + fmaxf(a0.y + pbv.y, 0.f) * wv.y
                 + fmaxf(a0.z + pbv.z, 0.f) * wv.z + fmaxf(a0.w + pbv.w, 0.f) * wv.w;
        float r1 = fmaxf(a1.x + pbv.x, 0.f) * wv.x + fmaxf(a1.y + pbv.y, 0.f) * wv.y
                 + fmaxf(a1.z + pbv.z, 0.f) * wv.z + fmaxf(a1.w + pbv.w, 0.f) * wv.w;
#pragma unroll
        for (int off = 16; off; off >>= 1) {
            r0 += __shfl_down_sync(0xffffffffu, r0, off);
            r1 += __shfl_down_sync(0xffffffffu, r1, off);
        }
        if (lane == 0) {
            out[ES_E(v0)] = 1.f / (1.f + expf(-(r0 + bias)));
            out[ES_E(v1)] = 1.f / (1.f + expf(-(r1 + bias)));
        }
    }
    if (k < end) {
        int v = g_es[k];
        float4 a = ldh4(pt2, (size_t)ES_S(v) * 32 + lane);
        float r = fmaxf(a.x + pbv.x, 0.f) * wv.x + fmaxf(a.y + pbv.y, 0.f) * wv.y
                + fmaxf(a.z + pbv.z, 0.f) * wv.z + fmaxf(a.w + pbv.w, 0.f) * wv.w;
#pragma unroll
        for (int off = 16; off; off >>= 1) r += __shfl_down_sync(0xffffffffu, r, off);
        if (lane == 0) out[ES_E(v)] = 1.f / (1.f + expf(-(r + bias)));
    }
}

// ---------------- launch ----------------
extern "C" void kernel_launch(void* const* d_in, const int* in_sizes, int n_in,
                              void* d_out, int out_size) {
    int off, iE, iT;
    if (in_sizes[0] == 2 * EE) { off = 2; iE = 0; iT = 1; }
    else                       { off = 0; iE = 24; iT = 25; }
    const int* ei = (const int*)d_in[iE];
    const int* et = (const int*)d_in[iT];
    const int* src = ei;
    const int* dst = ei + EE;
    const float* basis0 = (const float*)d_in[off + 0];
    const float* comp0  = (const float*)d_in[off + 1];
    const float* root0  = (const float*)d_in[off + 2];
    const float* rbias0 = (const float*)d_in[off + 3];
    const float* basis1 = (const float*)d_in[off + 4];
    const float* comp1  = (const float*)d_in[off + 5];
    const float* root1  = (const float*)d_in[off + 6];
    const float* rbias1 = (const float*)d_in[off + 7];
    const float* basis2 = (const float*)d_in[off + 8];
    const float* comp2  = (const float*)d_in[off + 9];
    const float* root2  = (const float*)d_in[off + 10];
    const float* rbias2 = (const float*)d_in[off + 11];
    const float* basis3 = (const float*)d_in[off + 12];
    const float* comp3  = (const float*)d_in[off + 13];
    const float* root3  = (const float*)d_in[off + 14];
    const float* rbias3 = (const float*)d_in[off + 15];
    const float* gw  = (const float*)d_in[off + 16];
    const float* gas = (const float*)d_in[off + 17];
    const float* gad = (const float*)d_in[off + 18];
    const float* gb  = (const float*)d_in[off + 19];
    const float* w1  = (const float*)d_in[off + 20];
    const float* b1  = (const float*)d_in[off + 21];
    const float* w2  = (const float*)d_in[off + 22];
    const float* b2  = (const float*)d_in[off + 23];
    float* out = (float*)d_out;

    pre_count_kernel<<<PRE_BLOCKS + CNT_BLOCKS + W1H_BLOCKS, 256>>>(
        basis0, comp0, basis1, comp1, basis2, comp2, basis3, comp3, dst, w1);
    scan_kernel<<<1, 1024>>>();
    scatter_kernel<<<CNT_BLOCKS, 256>>>(src, dst, et);

    l0d1_kernel<<<NN / 8, 256>>>(root0, rbias0, root1, rbias1);
    a1d2_kernel<<<NN / 4, 256>>>(root2, rbias2);
    a2d3_kernel<<<NN / 4, 256>>>(root3, rbias3);

    agg3_gath_kernel<<<NN / 16, 512>>>(gw, gas, gad);
    gatagg_kernel<<<NN / 16, 256>>>(gb);
    {
        dim3 grid((NN + MT - 1) / MT, 2);
        ptpb_mma_kernel<<<grid, 256>>>(b1);
    }
    edge_out_kernel<<<NN / 8, 256>>>(w2, b2, out);
}

// round 14
// speedup vs baseline: 1.0586x; 1.0586x over previous
#include <cuda_runtime.h>
#include <cuda_fp16.h>
#include <math.h>

#define NN 6000
#define EE 100000

// ---------------- device scratch (static, no allocation) ----------------
__device__ int g_deg[NN];          // zeroed at end of scan_kernel each launch (starts zeroed)
__device__ int g_rowptr[NN + 1];
__device__ int g_rank[EE];
__device__ int g_es[EE];           // packed per CSR slot: e | (src<<17) | (type<<30)

__device__ __align__(16) __half g_W0h[2 * NN * 32];  // layer-0 relation weights, fp16
__device__ __align__(16) float g_Wl1[2 * 32 * 64];
__device__ __align__(16) float g_Wl2[2 * 64 * 64];
__device__ __align__(16) float g_Wl3[2 * 64 * 32];
__device__ __align__(16) __half g_hrA16[2 * NN * 64];  // layers 1 (64-wide) / 3 (32-wide), fp16
__device__ __align__(16) __half g_hrB16[2 * NN * 64];  // layer 2 (64-wide), fp16
__device__ __align__(16) float g_rootout[NN * 64];
__device__ __align__(16) float g_rootout3[NN * 32];
__device__ __align__(16) __half g_hh[NN * 512];      // GAT hidden (fp16)
__device__ float g_asv[NN], g_adv[NN];
__device__ __align__(16) __half g_x16[NN * 512];     // GAT output features (fp16, GEMM A)
__device__ __align__(16) __half g_w1hT[256 * 512];   // w1 fp16, transposed [out][k]
__device__ __align__(16) float g_pt[NN * 128];       // x @ w1[0:512] (+ b1)
__device__ __align__(16) float g_pb[NN * 128];       // x @ w1[512:1024]

__device__ __forceinline__ float lrelu(float v) { return v > 0.f ? v : 0.2f * v; }

// load 4 consecutive halves as float4
__device__ __forceinline__ float4 ldh4(const uint2* base, size_t idx) {
    uint2 u = base[idx];
    __half2 p0 = *reinterpret_cast<__half2*>(&u.x);
    __half2 p1 = *reinterpret_cast<__half2*>(&u.y);
    float2 f0 = __half22float2(p0);
    float2 f1 = __half22float2(p1);
    return make_float4(f0.x, f0.y, f1.x, f1.y);
}

// ---------------- kernel 1: relation-weight precompute + degree count + w1->fp16T ----------------
#define W0_CNT (2 * NN * 32)
#define WL1_CNT (2 * 32 * 64)
#define WL2_CNT (2 * 64 * 64)
#define WL3_CNT (2 * 64 * 32)
#define PRE_CNT (W0_CNT + WL1_CNT + WL2_CNT + WL3_CNT)
#define PRE_BLOCKS (PRE_CNT / 256)              // exact
#define CNT_BLOCKS ((EE + 255) / 256)
#define W1H_BLOCKS ((256 * 512) / 256)          // 512

__global__ void pre_count_kernel(const float* __restrict__ basis0, const float* __restrict__ comp0,
                                 const float* __restrict__ basis1, const float* __restrict__ comp1,
                                 const float* __restrict__ basis2, const float* __restrict__ comp2,
                                 const float* __restrict__ basis3, const float* __restrict__ comp3,
                                 const int* __restrict__ dst, const float* __restrict__ w1) {
    int bid = blockIdx.x;
    if (bid >= PRE_BLOCKS + CNT_BLOCKS) {
        // w1 -> fp16 transposed: g_w1hT[o][i] = w1[(i + (o>=128?512:0))*128 + (o&127)]
        int idx = (bid - PRE_BLOCKS - CNT_BLOCKS) * 256 + threadIdx.x;
        int o = idx >> 9, i = idx & 511;
        g_w1hT[o * 512 + i] = __float2half(w1[(i + ((o >= 128) ? 512 : 0)) * 128 + (o & 127)]);
        return;
    }
    if (bid >= PRE_BLOCKS) {
        int e = (bid - PRE_BLOCKS) * 256 + threadIdx.x;
        if (e < EE) g_rank[e] = atomicAdd(&g_deg[dst[e]], 1);
        return;
    }
    int idx = bid * 256 + threadIdx.x;
    if (idx < W0_CNT) {
        int per = NN * 32;
        int r = idx / per, rem = idx - r * per;
        float v = 0.f;
#pragma unroll
        for (int b = 0; b < 4; b++) v += comp0[r * 4 + b] * basis0[b * per + rem];
        g_W0h[idx] = __float2half(v);
        return;
    }
    idx -= W0_CNT;
    if (idx < WL1_CNT) {
        int per = 32 * 64;
        int r = idx / per, rem = idx - r * per;
        float v = 0.f;
#pragma unroll
        for (int b = 0; b < 4; b++) v += comp1[r * 4 + b] * basis1[b * per + rem];
        g_Wl1[idx] = v;
        return;
    }
    idx -= WL1_CNT;
    if (idx < WL2_CNT) {
        int per = 64 * 64;
        int r = idx / per, rem = idx - r * per;
        float v = 0.f;
#pragma unroll
        for (int b = 0; b < 4; b++) v += comp2[r * 4 + b] * basis2[b * per + rem];
        g_Wl2[idx] = v;
        return;
    }
    idx -= WL2_CNT;
    {
        int per = 64 * 32;
        int r = idx / per, rem = idx - r * per;
        float v = 0.f;
#pragma unroll
        for (int b = 0; b < 4; b++) v += comp3[r * 4 + b] * basis3[b * per + rem];
        g_Wl3[idx] = v;
    }
}

// ---------------- kernel 2: single-pass scan (also re-zeroes deg for next launch) ----------------
__global__ void scan_kernel() {
    __shared__ int swsum[32];
    int tid = threadIdx.x, lane = tid & 31, wid = tid >> 5;
    int base = tid * 6;
    int v[6];
    int s = 0;
#pragma unroll
    for (int j = 0; j < 6; j++) {
        int i = base + j;
        v[j] = (i < NN) ? g_deg[i] : 0;
        s += v[j];
    }
    int x = s;
#pragma unroll
    for (int off = 1; off < 32; off <<= 1) {
        int t = __shfl_up_sync(0xffffffffu, x, off);
        if (lane >= off) x += t;
    }
    if (lane == 31) swsum[wid] = x;
    __syncthreads();
    if (wid == 0) {
        int y = swsum[lane];
#pragma unroll
        for (int off = 1; off < 32; off <<= 1) {
            int t = __shfl_up_sync(0xffffffffu, y, off);
            if (lane >= off) y += t;
        }
        swsum[lane] = y;
    }
    __syncthreads();
    int run = x - s + (wid ? swsum[wid - 1] : 0);
#pragma unroll
    for (int j = 0; j < 6; j++) {
        int i = base + j;
        run += v[j];
        if (i < NN) g_rowptr[i + 1] = run;
    }
    if (tid == 0) g_rowptr[0] = 0;
#pragma unroll
    for (int j = 0; j < 6; j++) {
        int i = base + j;
        if (i < NN) g_deg[i] = 0;   // restore invariant for next launch
    }
}

// ---------------- kernel 3: atomic-free scatter, packed slot ----------------
__global__ void scatter_kernel(const int* __restrict__ src, const int* __restrict__ dst,
                               const int* __restrict__ et) {
    int e = blockIdx.x * blockDim.x + threadIdx.x;
    if (e < EE) {
        int p = g_rowptr[dst[e]] + g_rank[e];
        g_es[p] = e | (src[e] << 17) | (et[e] << 30);
    }
}

#define ES_S(v) (((v) >> 17) & 0x1FFF)
#define ES_T(v) (((v) >> 30) & 1)
#define ES_E(v) ((v) & 0x1FFFF)

// ---------------- kernel 4: layer-0 agg (dual-edge half-warps, fp16 W0) + dense1 fused ----------
__global__ void l0d1_kernel(const float* __restrict__ root0, const float* __restrict__ rbias0,
                            const float* __restrict__ root1, const float* __restrict__ rbias1) {
    __shared__ float sx[8][32];
    int tid = threadIdx.x, w = tid >> 5, lane = tid & 31;
    int hl = lane & 15, side = lane >> 4;
    int node = blockIdx.x * 8 + w;
    {
        int beg = g_rowptr[node], end = g_rowptr[node + 1];
        float2 A0 = make_float2(0.f, 0.f), A1 = make_float2(0.f, 0.f);
        float C0 = 0.f, C1 = 0.f;
        int k = beg + side;
        for (; k + 2 < end; k += 4) {
            int v0 = g_es[k], v1 = g_es[k + 2];
            float2 f0 = __half22float2(*(const __half2*)(g_W0h + ES_T(v0) * (NN * 32) + ES_S(v0) * 32 + 2 * hl));
            float2 f1 = __half22float2(*(const __half2*)(g_W0h + ES_T(v1) * (NN * 32) + ES_S(v1) * 32 + 2 * hl));
            if (ES_T(v0)) { A1.x += f0.x; A1.y += f0.y; C1 += 1.f; }
            else          { A0.x += f0.x; A0.y += f0.y; C0 += 1.f; }
            if (ES_T(v1)) { A1.x += f1.x; A1.y += f1.y; C1 += 1.f; }
            else          { A0.x += f1.x; A0.y += f1.y; C0 += 1.f; }
        }
        if (k < end) {
            int v = g_es[k];
            float2 f = __half22float2(*(const __half2*)(g_W0h + ES_T(v) * (NN * 32) + ES_S(v) * 32 + 2 * hl));
            if (ES_T(v)) { A1.x += f.x; A1.y += f.y; C1 += 1.f; }
            else         { A0.x += f.x; A0.y += f.y; C0 += 1.f; }
        }
        A0.x += __shfl_xor_sync(0xffffffffu, A0.x, 16);
        A0.y += __shfl_xor_sync(0xffffffffu, A0.y, 16);
        A1.x += __shfl_xor_sync(0xffffffffu, A1.x, 16);
        A1.y += __shfl_xor_sync(0xffffffffu, A1.y, 16);
        C0 += __shfl_xor_sync(0xffffffffu, C0, 16);
        C1 += __shfl_xor_sync(0xffffffffu, C1, 16);
        if (side == 0) {
            int col = hl * 2;
            float i0 = 1.f / fmaxf(C0, 1.f), i1 = 1.f / fmaxf(C1, 1.f);
            float o0 = root0[node * 32 + col] + rbias0[col] + A0.x * i0 + A1.x * i1;
            float o1 = root0[node * 32 + col + 1] + rbias0[col + 1] + A0.y * i0 + A1.y * i1;
            sx[w][col] = tanhf(o0);
            sx[w][col + 1] = tanhf(o1);
        }
    }
    __syncthreads();
    // dense1: 8 nodes x 64 outputs = 512 outputs, 2 per thread; hrA16 fp16
#pragma unroll
    for (int t = tid; t < 512; t += 256) {
        int ln = t >> 6, o = t & 63;
        int nn = blockIdx.x * 8 + ln;
        float a0 = 0.f, a1 = 0.f, ar = 0.f;
#pragma unroll 8
        for (int i = 0; i < 32; i++) {
            float xv = sx[ln][i];
            a0 += xv * g_Wl1[i * 64 + o];
            a1 += xv * g_Wl1[32 * 64 + i * 64 + o];
            ar += xv * root1[i * 64 + o];
        }
        g_hrA16[nn * 64 + o] = __float2half(a0);
        g_hrA16[NN * 64 + nn * 64 + o] = __float2half(a1);
        g_rootout[nn * 64 + o] = ar + rbias1[o];
    }
}

// ---------------- kernel 5: agg1 (fp16 half2 lanes, warp/node) + dense2 fused ----------------
// 256 threads = 8 warps = 8 nodes. Each lane covers 2 cols via __half2.
__global__ void a1d2_kernel(const float* __restrict__ root2, const float* __restrict__ rbias2) {
    __shared__ float sx[8][64];
    int tid = threadIdx.x, w = tid >> 5, lane = tid & 31;
    int node = blockIdx.x * 8 + w;
    {
        int beg = g_rowptr[node], end = g_rowptr[node + 1];
        float2 A0 = make_float2(0.f, 0.f), A1 = make_float2(0.f, 0.f);
        float C0 = 0.f, C1 = 0.f;
        int k = beg;
        for (; k + 2 <= end; k += 2) {
            int v0 = g_es[k], v1 = g_es[k + 1];
            float2 f0 = __half22float2(*(const __half2*)(g_hrA16 + ES_T(v0) * (NN * 64) + ES_S(v0) * 64 + 2 * lane));
            float2 f1 = __half22float2(*(const __half2*)(g_hrA16 + ES_T(v1) * (NN * 64) + ES_S(v1) * 64 + 2 * lane));
            if (ES_T(v0)) { A1.x += f0.x; A1.y += f0.y; C1 += 1.f; }
            else          { A0.x += f0.x; A0.y += f0.y; C0 += 1.f; }
            if (ES_T(v1)) { A1.x += f1.x; A1.y += f1.y; C1 += 1.f; }
            else          { A0.x += f1.x; A0.y += f1.y; C0 += 1.f; }
        }
        if (k < end) {
            int v = g_es[k];
            float2 f = __half22float2(*(const __half2*)(g_hrA16 + ES_T(v) * (NN * 64) + ES_S(v) * 64 + 2 * lane));
            if (ES_T(v)) { A1.x += f.x; A1.y += f.y; C1 += 1.f; }
            else         { A0.x += f.x; A0.y += f.y; C0 += 1.f; }
        }
        int col = lane * 2;
        float i0 = 1.f / fmaxf(C0, 1.f), i1 = 1.f / fmaxf(C1, 1.f);
        float o0 = g_rootout[node * 64 + col] + A0.x * i0 + A1.x * i1;
        float o1 = g_rootout[node * 64 + col + 1] + A0.y * i0 + A1.y * i1;
        sx[w][col] = tanhf(o0);
        sx[w][col + 1] = tanhf(o1);
    }
    __syncthreads();
    // dense2: 8 nodes x 64 outputs = 512 outputs, 2 per thread; hrB16 fp16
#pragma unroll
    for (int t = tid; t < 512; t += 256) {
        int ln = t >> 6, o = t & 63;
        int nn = blockIdx.x * 8 + ln;
        float a0 = 0.f, a1 = 0.f, ar = 0.f;
#pragma unroll 8
        for (int i = 0; i < 64; i++) {
            float xv = sx[ln][i];
            a0 += xv * g_Wl2[i * 64 + o];
            a1 += xv * g_Wl2[64 * 64 + i * 64 + o];
            ar += xv * root2[i * 64 + o];
        }
        g_hrB16[nn * 64 + o] = __float2half(a0);
        g_hrB16[NN * 64 + nn * 64 + o] = __float2half(a1);
        g_rootout[nn * 64 + o] = ar + rbias2[o];
    }
}

// ---------------- kernel 6: agg2 (fp16 half2 lanes) + dense3 fused ----------------
__global__ void a2d3_kernel(const float* __restrict__ root3, const float* __restrict__ rbias3) {
    __shared__ float sx[8][64];
    int tid = threadIdx.x, w = tid >> 5, lane = tid & 31;
    int node = blockIdx.x * 8 + w;
    {
        int beg = g_rowptr[node], end = g_rowptr[node + 1];
        float2 A0 = make_float2(0.f, 0.f), A1 = make_float2(0.f, 0.f);
        float C0 = 0.f, C1 = 0.f;
        int k = beg;
        for (; k + 2 <= end; k += 2) {
            int v0 = g_es[k], v1 = g_es[k + 1];
            float2 f0 = __half22float2(*(const __half2*)(g_hrB16 + ES_T(v0) * (NN * 64) + ES_S(v0) * 64 + 2 * lane));
            float2 f1 = __half22float2(*(const __half2*)(g_hrB16 + ES_T(v1) * (NN * 64) + ES_S(v1) * 64 + 2 * lane));
            if (ES_T(v0)) { A1.x += f0.x; A1.y += f0.y; C1 += 1.f; }
            else          { A0.x += f0.x; A0.y += f0.y; C0 += 1.f; }
            if (ES_T(v1)) { A1.x += f1.x; A1.y += f1.y; C1 += 1.f; }
            else          { A0.x += f1.x; A0.y += f1.y; C0 += 1.f; }
        }
        if (k < end) {
            int v = g_es[k];
            float2 f = __half22float2(*(const __half2*)(g_hrB16 + ES_T(v) * (NN * 64) + ES_S(v) * 64 + 2 * lane));
            if (ES_T(v)) { A1.x += f.x; A1.y += f.y; C1 += 1.f; }
            else         { A0.x += f.x; A0.y += f.y; C0 += 1.f; }
        }
        int col = lane * 2;
        float i0 = 1.f / fmaxf(C0, 1.f), i1 = 1.f / fmaxf(C1, 1.f);
        float o0 = g_rootout[node * 64 + col] + A0.x * i0 + A1.x * i1;
        float o1 = g_rootout[node * 64 + col + 1] + A0.y * i0 + A1.y * i1;
        sx[w][col] = tanhf(o0);
        sx[w][col + 1] = tanhf(o1);
    }
    __syncthreads();
    // dense3: 8 nodes x 32 outputs = 256 outputs, one per thread; hrA16 32-wide
    {
        int ln3 = tid >> 5, o3 = tid & 31;
        int nn = blockIdx.x * 8 + ln3;
        float a0 = 0.f, a1 = 0.f, ar = 0.f;
#pragma unroll 8
        for (int i = 0; i < 64; i++) {
            float xv = sx[ln3][i];
            a0 += xv * g_Wl3[i * 32 + o3];
            a1 += xv * g_Wl3[64 * 32 + i * 32 + o3];
            ar += xv * root3[i * 32 + o3];
        }
        g_hrA16[nn * 32 + o3] = __float2half(a0);
        g_hrA16[NN * 32 + nn * 32 + o3] = __float2half(a1);
        g_rootout3[nn * 32 + o3] = ar + rbias3[o3];
    }
}

// ---------------- kernel 7: agg3 (dual-edge half-warps, fp16) + GAT h GEMM + asv/adv ----------
__global__ void agg3_gath_kernel(const float* __restrict__ gw,
                                 const float* __restrict__ as, const float* __restrict__ ad) {
    __shared__ __align__(16) float sx[16][32];
    __shared__ float s_as[16], s_ad[16];
    int tid = threadIdx.x;  // 512
    int node0 = blockIdx.x * 16;
    int w = tid >> 5, lane = tid & 31;
    int hl = lane & 15, side = lane >> 4;
    // phase 0: agg3, warp per node, dual-edge half-warps on fp16 32-wide hrA
    {
        int node = node0 + w;
        int beg = g_rowptr[node], end = g_rowptr[node + 1];
        float2 A0 = make_float2(0.f, 0.f), A1 = make_float2(0.f, 0.f);
        float C0 = 0.f, C1 = 0.f;
        int k = beg + side;
        for (; k + 2 < end; k += 4) {
            int v0 = g_es[k], v1 = g_es[k + 2];
            float2 f0 = __half22float2(*(const __half2*)(g_hrA16 + ES_T(v0) * (NN * 32) + ES_S(v0) * 32 + 2 * hl));
            float2 f1 = __half22float2(*(const __half2*)(g_hrA16 + ES_T(v1) * (NN * 32) + ES_S(v1) * 32 + 2 * hl));
            if (ES_T(v0)) { A1.x += f0.x; A1.y += f0.y; C1 += 1.f; }
            else          { A0.x += f0.x; A0.y += f0.y; C0 += 1.f; }
            if (ES_T(v1)) { A1.x += f1.x; A1.y += f1.y; C1 += 1.f; }
            else          { A0.x += f1.x; A0.y += f1.y; C0 += 1.f; }
        }
        if (k < end) {
            int v = g_es[k];
            float2 f = __half22float2(*(const __half2*)(g_hrA16 + ES_T(v) * (NN * 32) + ES_S(v) * 32 + 2 * hl));
            if (ES_T(v)) { A1.x += f.x; A1.y += f.y; C1 += 1.f; }
            else         { A0.x += f.x; A0.y += f.y; C0 += 1.f; }
        }
        A0.x += __shfl_xor_sync(0xffffffffu, A0.x, 16);
        A0.y += __shfl_xor_sync(0xffffffffu, A0.y, 16);
        A1.x += __shfl_xor_sync(0xffffffffu, A1.x, 16);
        A1.y += __shfl_xor_sync(0xffffffffu, A1.y, 16);
        C0 += __shfl_xor_sync(0xffffffffu, C0, 16);
        C1 += __shfl_xor_sync(0xffffffffu, C1, 16);
        if (side == 0) {
            int col = hl * 2;
            float i0 = 1.f / fmaxf(C0, 1.f), i1 = 1.f / fmaxf(C1, 1.f);
            float o0 = g_rootout3[node * 32 + col] + A0.x * i0 + A1.x * i1;
            float o1 = g_rootout3[node * 32 + col + 1] + A0.y * i0 + A1.y * i1;
            sx[w][col] = tanhf(o0);
            sx[w][col + 1] = tanhf(o1);
        }
    }
    if (tid < 16) { s_as[tid] = 0.f; s_ad[tid] = 0.f; }
    __syncthreads();
    // phase 1: GEMM 32 -> 512 with fused attention-logit dots
    int cg = tid & 127;
    int ng = tid >> 7;
    int col4 = cg * 4;
    int nbase = ng * 4;
    float acc[4][4];
#pragma unroll
    for (int a = 0; a < 4; a++)
#pragma unroll
        for (int b = 0; b < 4; b++) acc[a][b] = 0.f;
#pragma unroll 8
    for (int i = 0; i < 32; i++) {
        float4 wv = *(const float4*)(gw + i * 512 + col4);
        float x0 = sx[nbase + 0][i], x1 = sx[nbase + 1][i];
        float x2 = sx[nbase + 2][i], x3 = sx[nbase + 3][i];
        acc[0][0] += x0 * wv.x; acc[0][1] += x0 * wv.y; acc[0][2] += x0 * wv.z; acc[0][3] += x0 * wv.w;
        acc[1][0] += x1 * wv.x; acc[1][1] += x1 * wv.y; acc[1][2] += x1 * wv.z; acc[1][3] += x1 * wv.w;
        acc[2][0] += x2 * wv.x; acc[2][1] += x2 * wv.y; acc[2][2] += x2 * wv.z; acc[2][3] += x2 * wv.w;
        acc[3][0] += x3 * wv.x; acc[3][1] += x3 * wv.y; acc[3][2] += x3 * wv.z; acc[3][3] += x3 * wv.w;
    }
#pragma unroll
    for (int a = 0; a < 4; a++) {
        int nn = node0 + nbase + a;
        __half2 h0 = __floats2half2_rn(acc[a][0], acc[a][1]);
        __half2 h1 = __floats2half2_rn(acc[a][2], acc[a][3]);
        uint2 u;
        u.x = *reinterpret_cast<unsigned*>(&h0);
        u.y = *reinterpret_cast<unsigned*>(&h1);
        *reinterpret_cast<uint2*>(g_hh + (size_t)nn * 512 + col4) = u;
    }
    float4 av = *(const float4*)(as + col4);
    float4 dv = *(const float4*)(ad + col4);
#pragma unroll
    for (int a = 0; a < 4; a++) {
        float ps = acc[a][0] * av.x + acc[a][1] * av.y + acc[a][2] * av.z + acc[a][3] * av.w;
        float pd = acc[a][0] * dv.x + acc[a][1] * dv.y + acc[a][2] * dv.z + acc[a][3] * dv.w;
#pragma unroll
        for (int off = 16; off; off >>= 1) {
            ps += __shfl_down_sync(0xffffffffu, ps, off);
            pd += __shfl_down_sync(0xffffffffu, pd, off);
        }
        if (lane == 0) {
            atomicAdd(&s_as[nbase + a], ps);
            atomicAdd(&s_ad[nbase + a], pd);
        }
    }
    __syncthreads();
    if (tid < 16) {
        int nn = node0 + tid;
        g_asv[nn] = s_as[tid];
        g_adv[nn] = s_ad[tid];
    }
}

// ---------------- kernel 8: GAT softmax-agg -> fp16 node features ----------------
__global__ void gatagg_kernel(const float* __restrict__ gbias) {
    __shared__ float sex[2][64];
    __shared__ int ssrc[2][64];
    int tid = threadIdx.x;
    int node0 = blockIdx.x * 16;
    int g = tid >> 7;
    int gtid = tid & 127;
    const uint2* h2 = (const uint2*)g_hh;   // 4 halves per uint2
    float4 gb4 = ((const float4*)gbias)[gtid];
    for (int k = 0; k < 8; k++) {
        int n = node0 + g * 8 + k;
        int beg = g_rowptr[n], deg = g_rowptr[n + 1] - beg;
        float advn = g_adv[n];
        float exself = expf(lrelu(g_asv[n] + advn));
        float4 hs = ldh4(h2, (size_t)n * 128 + gtid);
        float ax = exself * hs.x, ay = exself * hs.y, az = exself * hs.z, aw = exself * hs.w;
        float dsum = exself;
        for (int base = 0; base < deg; base += 64) {
            int cnt = min(64, deg - base);
            if (gtid < cnt) {
                int v = g_es[beg + base + gtid];
                int s = ES_S(v);
                ssrc[g][gtid] = s;
                sex[g][gtid] = expf(lrelu(g_asv[s] + advn));
            }
            asm volatile("bar.sync %0, %1;" :: "r"(g + 1), "r"(128) : "memory");
            for (int j = 0; j < cnt; j++) {
                float exv = sex[g][j];
                float4 hv = ldh4(h2, (size_t)ssrc[g][j] * 128 + gtid);
                ax += exv * hv.x; ay += exv * hv.y; az += exv * hv.z; aw += exv * hv.w;
                dsum += exv;
            }
            asm volatile("bar.sync %0, %1;" :: "r"(g + 1), "r"(128) : "memory");
        }
        float inv = 1.f / fmaxf(dsum, 1e-16f);
        float ox = fmaxf(ax * inv + gb4.x, 0.f);
        float oy = fmaxf(ay * inv + gb4.y, 0.f);
        float oz = fmaxf(az * inv + gb4.z, 0.f);
        float ow = fmaxf(aw * inv + gb4.w, 0.f);
        __half2 p0 = __floats2half2_rn(ox, oy);
        __half2 p1 = __floats2half2_rn(oz, ow);
        uint2 u;
        u.x = *reinterpret_cast<unsigned*>(&p0);
        u.y = *reinterpret_cast<unsigned*>(&p1);
        *reinterpret_cast<uint2*>(g_x16 + (size_t)n * 512 + gtid * 4) = u;
    }
}

// ---------------- kernel 9: pt/pb GEMM via tensor cores (m16n8k16 fp16/fp32) ----------------
#define MT 32
__global__ void ptpb_mma_kernel(const float* __restrict__ b1) {
    __shared__ __align__(16) __half As[MT][72];
    __shared__ __align__(16) __half Bs[128][72];
    int tid = threadIdx.x;
    int node0 = blockIdx.x * MT;
    int nblk = blockIdx.y;
    int w = tid >> 5, lane = tid & 31;
    int wm = (w >> 2) * 16;
    int wn = (w & 3) * 32;
    int grp = lane >> 2, tig = lane & 3;
    float acc[4][4];
#pragma unroll
    for (int a = 0; a < 4; a++)
#pragma unroll
        for (int b = 0; b < 4; b++) acc[a][b] = 0.f;
    const __half* wT = g_w1hT + (size_t)nblk * 128 * 512;
#pragma unroll 1
    for (int kt = 0; kt < 8; kt++) {
        int k0 = kt * 64;
        {
            int m = tid >> 3, kc = (tid & 7) * 8;
            int node = node0 + m;
            uint4 v = make_uint4(0u, 0u, 0u, 0u);
            if (node < NN) v = *(const uint4*)(g_x16 + (size_t)node * 512 + k0 + kc);
            *(uint4*)&As[m][kc] = v;
        }
        {
            int n = tid >> 1, kc = (tid & 1) * 32;
            const __half* src = wT + (size_t)n * 512 + k0 + kc;
            uint4 v0 = ((const uint4*)src)[0];
            uint4 v1 = ((const uint4*)src)[1];
            uint4 v2 = ((const uint4*)src)[2];
            uint4 v3 = ((const uint4*)src)[3];
            *(uint4*)&Bs[n][kc] = v0;
            *(uint4*)&Bs[n][kc + 8] = v1;
            *(uint4*)&Bs[n][kc + 16] = v2;
            *(uint4*)&Bs[n][kc + 24] = v3;
        }
        __syncthreads();
#pragma unroll
        for (int ks = 0; ks < 4; ks++) {
            int kk = ks * 16 + tig * 2;
            unsigned a0 = *(const unsigned*)&As[wm + grp][kk];
            unsigned a1 = *(const unsigned*)&As[wm + grp + 8][kk];
            unsigned a2 = *(const unsigned*)&As[wm + grp][kk + 8];
            unsigned a3 = *(const unsigned*)&As[wm + grp + 8][kk + 8];
#pragma unroll
            for (int nf = 0; nf < 4; nf++) {
                int n8 = wn + nf * 8 + grp;
                unsigned b0 = *(const unsigned*)&Bs[n8][kk];
                unsigned b1r = *(const unsigned*)&Bs[n8][kk + 8];
                asm volatile(
                    "mma.sync.aligned.m16n8k16.row.col.f32.f16.f16.f32 "
                    "{%0,%1,%2,%3}, {%4,%5,%6,%7}, {%8,%9}, {%0,%1,%2,%3};"
                    : "+f"(acc[nf][0]), "+f"(acc[nf][1]), "+f"(acc[nf][2]), "+f"(acc[nf][3])
                    : "r"(a0), "r"(a1), "r"(a2), "r"(a3), "r"(b0), "r"(b1r));
            }
        }
        __syncthreads();
    }
#pragma unroll
    for (int nf = 0; nf < 4; nf++) {
        int ncol = nblk * 128 + wn + nf * 8 + tig * 2;   // global col 0..255
        float bx_ = 0.f, by_ = 0.f;
        float* obase;
        int oc;
        if (ncol < 128) {
            obase = g_pt; oc = ncol;
            float2 bb = *(const float2*)(b1 + ncol);
            bx_ = bb.x; by_ = bb.y;
        } else {
            obase = g_pb; oc = ncol - 128;
        }
        int n0 = node0 + wm + grp;
        if (n0 < NN)
            *(float2*)(obase + (size_t)n0 * 128 + oc) = make_float2(acc[nf][0] + bx_, acc[nf][1] + by_);
        int n1 = n0 + 8;
        if (n1 < NN)
            *(float2*)(obase + (size_t)n1 * 128 + oc) = make_float2(acc[nf][2] + bx_, acc[nf][3] + by_);
    }
}

// ---------------- kernel 10: per-edge output, CSR order (pb[dst] loaded once/warp) ----------------
__global__ void edge_out_kernel(const float* __restrict__ w2, const float* __restrict__ b2,
                                float* __restrict__ out) {
    int tid = threadIdx.x, w = tid >> 5, lane = tid & 31;
    int node = blockIdx.x * 8 + w;
    int beg = g_rowptr[node], end = g_rowptr[node + 1];
    if (beg == end) return;
    const float4* pt4 = (const float4*)g_pt;
    float4 pbv = ((const float4*)g_pb)[(size_t)node * 32 + lane];
    float4 wv = ((const float4*)w2)[lane];
    float bias = b2[0];
    int k = beg;
    for (; k + 2 <= end; k += 2) {
        int v0 = g_es[k], v1 = g_es[k + 1];
        float4 a0 = pt4[(size_t)ES_S(v0) * 32 + lane];
        float4 a1 = pt4[(size_t)ES_S(v1) * 32 + lane];
        float r0 = fmaxf(a0.x + pbv.x, 0.f) * wv.x + fmaxf(a0.y + pbv.y, 0.f) * wv.y
                 + fmaxf(a0.z + pbv.z, 0.f) * wv.z + fmaxf(a0.w + pbv.w, 0.f) * wv.w;
        float r1 = fmaxf(a1.x + pbv.x, 0.f) * wv.x + fmaxf(a1.y + pbv.y, 0.f) * wv.y
                 + fmaxf(a1.z + pbv.z, 0.f) * wv.z + fmaxf(a1.w + pbv.w, 0.f) * wv.w;
#pragma unroll
        for (int off = 16; off; off >>= 1) {
            r0 += __shfl_down_sync(0xffffffffu, r0, off);
            r1 += __shfl_down_sync(0xffffffffu, r1, off);
        }
        if (lane == 0) {
            out[ES_E(v0)] = 1.f / (1.f + expf(-(r0 + bias)));
            out[ES_E(v1)] = 1.f / (1.f + expf(-(r1 + bias)));
        }
    }
    if (k < end) {
        int v = g_es[k];
        float4 a = pt4[(size_t)ES_S(v) * 32 + lane];
        float r = fmaxf(a.x + pbv.x, 0.f) * wv.x + fmaxf(a.y + pbv.y, 0.f) * wv.y
                + fmaxf(a.z + pbv.z, 0.f) * wv.z + fmaxf(a.w + pbv.w, 0.f) * wv.w;
#pragma unroll
        for (int off = 16; off; off >>= 1) r += __shfl_down_sync(0xffffffffu, r, off);
        if (lane == 0) out[ES_E(v)] = 1.f / (1.f + expf(-(r + bias)));
    }
}

// ---------------- launch ----------------
extern "C" void kernel_launch(void* const* d_in, const int* in_sizes, int n_in,
                              void* d_out, int out_size) {
    int off, iE, iT;
    if (in_sizes[0] == 2 * EE) { off = 2; iE = 0; iT = 1; }
    else                       { off = 0; iE = 24; iT = 25; }
    const int* ei = (const int*)d_in[iE];
    const int* et = (const int*)d_in[iT];
    const int* src = ei;
    const int* dst = ei + EE;
    const float* basis0 = (const float*)d_in[off + 0];
    const float* comp0  = (const float*)d_in[off + 1];
    const float* root0  = (const float*)d_in[off + 2];
    const float* rbias0 = (const float*)d_in[off + 3];
    const float* basis1 = (const float*)d_in[off + 4];
    const float* comp1  = (const float*)d_in[off + 5];
    const float* root1  = (const float*)d_in[off + 6];
    const float* rbias1 = (const float*)d_in[off + 7];
    const float* basis2 = (const float*)d_in[off + 8];
    const float* comp2  = (const float*)d_in[off + 9];
    const float* root2  = (const float*)d_in[off + 10];
    const float* rbias2 = (const float*)d_in[off + 11];
    const float* basis3 = (const float*)d_in[off + 12];
    const float* comp3  = (const float*)d_in[off + 13];
    const float* root3  = (const float*)d_in[off + 14];
    const float* rbias3 = (const float*)d_in[off + 15];
    const float* gw  = (const float*)d_in[off + 16];
    const float* gas = (const float*)d_in[off + 17];
    const float* gad = (const float*)d_in[off + 18];
    const float* gb  = (const float*)d_in[off + 19];
    const float* w1  = (const float*)d_in[off + 20];
    const float* b1  = (const float*)d_in[off + 21];
    const float* w2  = (const float*)d_in[off + 22];
    const float* b2  = (const float*)d_in[off + 23];
    float* out = (float*)d_out;

    pre_count_kernel<<<PRE_BLOCKS + CNT_BLOCKS + W1H_BLOCKS, 256>>>(
        basis0, comp0, basis1, comp1, basis2, comp2, basis3, comp3, dst, w1);
    scan_kernel<<<1, 1024>>>();
    scatter_kernel<<<CNT_BLOCKS, 256>>>(src, dst, et);

    l0d1_kernel<<<NN / 8, 256>>>(root0, rbias0, root1, rbias1);
    a1d2_kernel<<<NN / 8, 256>>>(root2, rbias2);
    a2d3_kernel<<<NN / 8, 256>>>(root3, rbias3);

    agg3_gath_kernel<<<NN / 16, 512>>>(gw, gas, gad);
    gatagg_kernel<<<NN / 16, 256>>>(gb);
    {
        dim3 grid((NN + MT - 1) / MT, 2);
        ptpb_mma_kernel<<<grid, 256>>>(b1);
    }
    edge_out_kernel<<<NN / 8, 256>>>(w2, b2, out);
}

// round 15
// speedup vs baseline: 1.0732x; 1.0138x over previous
#include <cuda_runtime.h>
#include <cuda_fp16.h>
#include <math.h>

#define NN 6000
#define EE 100000

// ---------------- device scratch (static, no allocation) ----------------
__device__ int g_deg[NN];          // zeroed at end of scan_kernel each launch (starts zeroed)
__device__ int g_rowptr[NN + 1];
__device__ int g_rank[EE];
__device__ int g_es[EE];           // packed per CSR slot: e | (src<<17) | (type<<30)

__device__ __align__(16) __half g_W0h[2 * NN * 32];  // layer-0 relation weights, fp16
__device__ __align__(16) float g_Wl1[2 * 32 * 64];
__device__ __align__(16) float g_Wl2[2 * 64 * 64];
__device__ __align__(16) float g_Wl3[2 * 64 * 32];
__device__ __align__(16) __half g_hrA16[2 * NN * 64];  // layers 1 (64-wide) / 3 (32-wide), fp16
__device__ __align__(16) __half g_hrB16[2 * NN * 64];  // layer 2 (64-wide), fp16
__device__ __align__(16) float g_rootout[NN * 64];
__device__ __align__(16) float g_rootout3[NN * 32];
__device__ __align__(16) __half g_hh[NN * 512];      // GAT hidden (fp16)
__device__ float g_asv[NN], g_adv[NN];
__device__ __align__(16) __half g_x16[NN * 512];     // GAT output features (fp16, GEMM A)
__device__ __align__(16) __half g_w1hT[256 * 512];   // w1 fp16, transposed [out][k]
__device__ __align__(16) float g_pt[NN * 128];       // x @ w1[0:512] (+ b1)
__device__ __align__(16) float g_pb[NN * 128];       // x @ w1[512:1024]

__device__ __forceinline__ float lrelu(float v) { return v > 0.f ? v : 0.2f * v; }

// load 4 consecutive halves as float4
__device__ __forceinline__ float4 ldh4(const uint2* base, size_t idx) {
    uint2 u = base[idx];
    __half2 p0 = *reinterpret_cast<__half2*>(&u.x);
    __half2 p1 = *reinterpret_cast<__half2*>(&u.y);
    float2 f0 = __half22float2(p0);
    float2 f1 = __half22float2(p1);
    return make_float4(f0.x, f0.y, f1.x, f1.y);
}

// ---------------- kernel 1: relation-weight precompute + degree count + w1->fp16T ----------------
#define W0_CNT (2 * NN * 32)
#define WL1_CNT (2 * 32 * 64)
#define WL2_CNT (2 * 64 * 64)
#define WL3_CNT (2 * 64 * 32)
#define PRE_CNT (W0_CNT + WL1_CNT + WL2_CNT + WL3_CNT)
#define PRE_BLOCKS (PRE_CNT / 256)              // exact
#define CNT_BLOCKS ((EE + 255) / 256)
#define W1H_BLOCKS ((256 * 512) / 256)          // 512

__global__ void pre_count_kernel(const float* __restrict__ basis0, const float* __restrict__ comp0,
                                 const float* __restrict__ basis1, const float* __restrict__ comp1,
                                 const float* __restrict__ basis2, const float* __restrict__ comp2,
                                 const float* __restrict__ basis3, const float* __restrict__ comp3,
                                 const int* __restrict__ dst, const float* __restrict__ w1) {
    int bid = blockIdx.x;
    if (bid >= PRE_BLOCKS + CNT_BLOCKS) {
        int idx = (bid - PRE_BLOCKS - CNT_BLOCKS) * 256 + threadIdx.x;
        int o = idx >> 9, i = idx & 511;
        g_w1hT[o * 512 + i] = __float2half(w1[(i + ((o >= 128) ? 512 : 0)) * 128 + (o & 127)]);
        return;
    }
    if (bid >= PRE_BLOCKS) {
        int e = (bid - PRE_BLOCKS) * 256 + threadIdx.x;
        if (e < EE) g_rank[e] = atomicAdd(&g_deg[dst[e]], 1);
        return;
    }
    int idx = bid * 256 + threadIdx.x;
    if (idx < W0_CNT) {
        int per = NN * 32;
        int r = idx / per, rem = idx - r * per;
        float v = 0.f;
#pragma unroll
        for (int b = 0; b < 4; b++) v += comp0[r * 4 + b] * basis0[b * per + rem];
        g_W0h[idx] = __float2half(v);
        return;
    }
    idx -= W0_CNT;
    if (idx < WL1_CNT) {
        int per = 32 * 64;
        int r = idx / per, rem = idx - r * per;
        float v = 0.f;
#pragma unroll
        for (int b = 0; b < 4; b++) v += comp1[r * 4 + b] * basis1[b * per + rem];
        g_Wl1[idx] = v;
        return;
    }
    idx -= WL1_CNT;
    if (idx < WL2_CNT) {
        int per = 64 * 64;
        int r = idx / per, rem = idx - r * per;
        float v = 0.f;
#pragma unroll
        for (int b = 0; b < 4; b++) v += comp2[r * 4 + b] * basis2[b * per + rem];
        g_Wl2[idx] = v;
        return;
    }
    idx -= WL2_CNT;
    {
        int per = 64 * 32;
        int r = idx / per, rem = idx - r * per;
        float v = 0.f;
#pragma unroll
        for (int b = 0; b < 4; b++) v += comp3[r * 4 + b] * basis3[b * per + rem];
        g_Wl3[idx] = v;
    }
}

// ---------------- kernel 2: single-pass scan (also re-zeroes deg for next launch) ----------------
__global__ void scan_kernel() {
    __shared__ int swsum[32];
    int tid = threadIdx.x, lane = tid & 31, wid = tid >> 5;
    int base = tid * 6;
    int v[6];
    int s = 0;
#pragma unroll
    for (int j = 0; j < 6; j++) {
        int i = base + j;
        v[j] = (i < NN) ? g_deg[i] : 0;
        s += v[j];
    }
    int x = s;
#pragma unroll
    for (int off = 1; off < 32; off <<= 1) {
        int t = __shfl_up_sync(0xffffffffu, x, off);
        if (lane >= off) x += t;
    }
    if (lane == 31) swsum[wid] = x;
    __syncthreads();
    if (wid == 0) {
        int y = swsum[lane];
#pragma unroll
        for (int off = 1; off < 32; off <<= 1) {
            int t = __shfl_up_sync(0xffffffffu, y, off);
            if (lane >= off) y += t;
        }
        swsum[lane] = y;
    }
    __syncthreads();
    int run = x - s + (wid ? swsum[wid - 1] : 0);
#pragma unroll
    for (int j = 0; j < 6; j++) {
        int i = base + j;
        run += v[j];
        if (i < NN) g_rowptr[i + 1] = run;
    }
    if (tid == 0) g_rowptr[0] = 0;
#pragma unroll
    for (int j = 0; j < 6; j++) {
        int i = base + j;
        if (i < NN) g_deg[i] = 0;   // restore invariant for next launch
    }
}

// ---------------- kernel 3: atomic-free scatter, packed slot ----------------
__global__ void scatter_kernel(const int* __restrict__ src, const int* __restrict__ dst,
                               const int* __restrict__ et) {
    int e = blockIdx.x * blockDim.x + threadIdx.x;
    if (e < EE) {
        int p = g_rowptr[dst[e]] + g_rank[e];
        g_es[p] = e | (src[e] << 17) | (et[e] << 30);
    }
}

#define ES_S(v) (((v) >> 17) & 0x1FFF)
#define ES_T(v) (((v) >> 30) & 1)
#define ES_E(v) ((v) & 0x1FFFF)

// quad-edge quarter-warp 32-wide fp16 aggregation: 8 lanes x uint2 cover a row,
// 4 edges per warp-LDG, 2 iterations in flight. Returns full sums in all lanes.
__device__ __forceinline__ void agg32_quad(const uint2* rows, int beg, int end,
                                           int hl, int side,
                                           float4& A0, float4& A1, float& C0, float& C1) {
    int k = beg + side;
    for (; k + 4 < end; k += 8) {
        int v0 = g_es[k], v1 = g_es[k + 4];
        float4 f0 = ldh4(rows, (size_t)(ES_T(v0) * NN + ES_S(v0)) * 8 + hl);
        float4 f1 = ldh4(rows, (size_t)(ES_T(v1) * NN + ES_S(v1)) * 8 + hl);
        if (ES_T(v0)) { A1.x += f0.x; A1.y += f0.y; A1.z += f0.z; A1.w += f0.w; C1 += 1.f; }
        else          { A0.x += f0.x; A0.y += f0.y; A0.z += f0.z; A0.w += f0.w; C0 += 1.f; }
        if (ES_T(v1)) { A1.x += f1.x; A1.y += f1.y; A1.z += f1.z; A1.w += f1.w; C1 += 1.f; }
        else          { A0.x += f1.x; A0.y += f1.y; A0.z += f1.z; A0.w += f1.w; C0 += 1.f; }
    }
    if (k < end) {
        int v = g_es[k];
        float4 f = ldh4(rows, (size_t)(ES_T(v) * NN + ES_S(v)) * 8 + hl);
        if (ES_T(v)) { A1.x += f.x; A1.y += f.y; A1.z += f.z; A1.w += f.w; C1 += 1.f; }
        else         { A0.x += f.x; A0.y += f.y; A0.z += f.z; A0.w += f.w; C0 += 1.f; }
    }
#pragma unroll
    for (int off = 8; off <= 16; off <<= 1) {
        A0.x += __shfl_xor_sync(0xffffffffu, A0.x, off);
        A0.y += __shfl_xor_sync(0xffffffffu, A0.y, off);
        A0.z += __shfl_xor_sync(0xffffffffu, A0.z, off);
        A0.w += __shfl_xor_sync(0xffffffffu, A0.w, off);
        A1.x += __shfl_xor_sync(0xffffffffu, A1.x, off);
        A1.y += __shfl_xor_sync(0xffffffffu, A1.y, off);
        A1.z += __shfl_xor_sync(0xffffffffu, A1.z, off);
        A1.w += __shfl_xor_sync(0xffffffffu, A1.w, off);
        C0 += __shfl_xor_sync(0xffffffffu, C0, off);
        C1 += __shfl_xor_sync(0xffffffffu, C1, off);
    }
}

// dual-edge half-warp 64-wide fp16 aggregation: 16 lanes x uint2 cover a row,
// 2 edges per warp-LDG, 2 iterations in flight.
__device__ __forceinline__ void agg64_dual(const uint2* rows, int beg, int end,
                                           int hl, int side,
                                           float4& A0, float4& A1, float& C0, float& C1) {
    int k = beg + side;
    for (; k + 2 < end; k += 4) {
        int v0 = g_es[k], v1 = g_es[k + 2];
        float4 f0 = ldh4(rows, (size_t)(ES_T(v0) * NN + ES_S(v0)) * 16 + hl);
        float4 f1 = ldh4(rows, (size_t)(ES_T(v1) * NN + ES_S(v1)) * 16 + hl);
        if (ES_T(v0)) { A1.x += f0.x; A1.y += f0.y; A1.z += f0.z; A1.w += f0.w; C1 += 1.f; }
        else          { A0.x += f0.x; A0.y += f0.y; A0.z += f0.z; A0.w += f0.w; C0 += 1.f; }
        if (ES_T(v1)) { A1.x += f1.x; A1.y += f1.y; A1.z += f1.z; A1.w += f1.w; C1 += 1.f; }
        else          { A0.x += f1.x; A0.y += f1.y; A0.z += f1.z; A0.w += f1.w; C0 += 1.f; }
    }
    if (k < end) {
        int v = g_es[k];
        float4 f = ldh4(rows, (size_t)(ES_T(v) * NN + ES_S(v)) * 16 + hl);
        if (ES_T(v)) { A1.x += f.x; A1.y += f.y; A1.z += f.z; A1.w += f.w; C1 += 1.f; }
        else         { A0.x += f.x; A0.y += f.y; A0.z += f.z; A0.w += f.w; C0 += 1.f; }
    }
    A0.x += __shfl_xor_sync(0xffffffffu, A0.x, 16);
    A0.y += __shfl_xor_sync(0xffffffffu, A0.y, 16);
    A0.z += __shfl_xor_sync(0xffffffffu, A0.z, 16);
    A0.w += __shfl_xor_sync(0xffffffffu, A0.w, 16);
    A1.x += __shfl_xor_sync(0xffffffffu, A1.x, 16);
    A1.y += __shfl_xor_sync(0xffffffffu, A1.y, 16);
    A1.z += __shfl_xor_sync(0xffffffffu, A1.z, 16);
    A1.w += __shfl_xor_sync(0xffffffffu, A1.w, 16);
    C0 += __shfl_xor_sync(0xffffffffu, C0, 16);
    C1 += __shfl_xor_sync(0xffffffffu, C1, 16);
}

// ---------------- kernel 4: layer-0 agg (quad-edge quarter-warps) + dense1 fused ----------
__global__ void l0d1_kernel(const float* __restrict__ root0, const float* __restrict__ rbias0,
                            const float* __restrict__ root1, const float* __restrict__ rbias1) {
    __shared__ __align__(16) float sx[8][32];
    int tid = threadIdx.x, w = tid >> 5, lane = tid & 31;
    int hl = lane & 7, side = lane >> 3;
    int node = blockIdx.x * 8 + w;
    {
        int beg = g_rowptr[node], end = g_rowptr[node + 1];
        float4 A0 = make_float4(0.f, 0.f, 0.f, 0.f), A1 = A0;
        float C0 = 0.f, C1 = 0.f;
        agg32_quad((const uint2*)g_W0h, beg, end, hl, side, A0, A1, C0, C1);
        if (side == 0) {
            int col = hl * 4;
            float i0 = 1.f / fmaxf(C0, 1.f), i1 = 1.f / fmaxf(C1, 1.f);
            float4 r = *(const float4*)(root0 + node * 32 + col);
            float4 rb = *(const float4*)(rbias0 + col);
            sx[w][col + 0] = tanhf(r.x + rb.x + A0.x * i0 + A1.x * i1);
            sx[w][col + 1] = tanhf(r.y + rb.y + A0.y * i0 + A1.y * i1);
            sx[w][col + 2] = tanhf(r.z + rb.z + A0.z * i0 + A1.z * i1);
            sx[w][col + 3] = tanhf(r.w + rb.w + A0.w * i0 + A1.w * i1);
        }
    }
    __syncthreads();
    // dense1: 8 nodes x 64 outputs = 512 outputs, 2 per thread; hrA16 fp16
#pragma unroll
    for (int t = tid; t < 512; t += 256) {
        int ln = t >> 6, o = t & 63;
        int nn = blockIdx.x * 8 + ln;
        float a0 = 0.f, a1 = 0.f, ar = 0.f;
#pragma unroll 8
        for (int i = 0; i < 32; i++) {
            float xv = sx[ln][i];
            a0 += xv * g_Wl1[i * 64 + o];
            a1 += xv * g_Wl1[32 * 64 + i * 64 + o];
            ar += xv * root1[i * 64 + o];
        }
        g_hrA16[nn * 64 + o] = __float2half(a0);
        g_hrA16[NN * 64 + nn * 64 + o] = __float2half(a1);
        g_rootout[nn * 64 + o] = ar + rbias1[o];
    }
}

// ---------------- kernel 5: agg1 (dual-edge half-warps) + dense2 fused ----------------
__global__ void a1d2_kernel(const float* __restrict__ root2, const float* __restrict__ rbias2) {
    __shared__ __align__(16) float sx[8][64];
    int tid = threadIdx.x, w = tid >> 5, lane = tid & 31;
    int hl = lane & 15, side = lane >> 4;
    int node = blockIdx.x * 8 + w;
    {
        int beg = g_rowptr[node], end = g_rowptr[node + 1];
        float4 A0 = make_float4(0.f, 0.f, 0.f, 0.f), A1 = A0;
        float C0 = 0.f, C1 = 0.f;
        agg64_dual((const uint2*)g_hrA16, beg, end, hl, side, A0, A1, C0, C1);
        if (side == 0) {
            int col = hl * 4;
            float i0 = 1.f / fmaxf(C0, 1.f), i1 = 1.f / fmaxf(C1, 1.f);
            float4 r = *(const float4*)(g_rootout + node * 64 + col);
            sx[w][col + 0] = tanhf(r.x + A0.x * i0 + A1.x * i1);
            sx[w][col + 1] = tanhf(r.y + A0.y * i0 + A1.y * i1);
            sx[w][col + 2] = tanhf(r.z + A0.z * i0 + A1.z * i1);
            sx[w][col + 3] = tanhf(r.w + A0.w * i0 + A1.w * i1);
        }
    }
    __syncthreads();
    // dense2: 8 nodes x 64 outputs = 512 outputs, 2 per thread; hrB16 fp16
#pragma unroll
    for (int t = tid; t < 512; t += 256) {
        int ln = t >> 6, o = t & 63;
        int nn = blockIdx.x * 8 + ln;
        float a0 = 0.f, a1 = 0.f, ar = 0.f;
#pragma unroll 8
        for (int i = 0; i < 64; i++) {
            float xv = sx[ln][i];
            a0 += xv * g_Wl2[i * 64 + o];
            a1 += xv * g_Wl2[64 * 64 + i * 64 + o];
            ar += xv * root2[i * 64 + o];
        }
        g_hrB16[nn * 64 + o] = __float2half(a0);
        g_hrB16[NN * 64 + nn * 64 + o] = __float2half(a1);
        g_rootout[nn * 64 + o] = ar + rbias2[o];
    }
}

// ---------------- kernel 6: agg2 (dual-edge half-warps) + dense3 fused ----------------
__global__ void a2d3_kernel(const float* __restrict__ root3, const float* __restrict__ rbias3) {
    __shared__ __align__(16) float sx[8][64];
    int tid = threadIdx.x, w = tid >> 5, lane = tid & 31;
    int hl = lane & 15, side = lane >> 4;
    int node = blockIdx.x * 8 + w;
    {
        int beg = g_rowptr[node], end = g_rowptr[node + 1];
        float4 A0 = make_float4(0.f, 0.f, 0.f, 0.f), A1 = A0;
        float C0 = 0.f, C1 = 0.f;
        agg64_dual((const uint2*)g_hrB16, beg, end, hl, side, A0, A1, C0, C1);
        if (side == 0) {
            int col = hl * 4;
            float i0 = 1.f / fmaxf(C0, 1.f), i1 = 1.f / fmaxf(C1, 1.f);
            float4 r = *(const float4*)(g_rootout + node * 64 + col);
            sx[w][col + 0] = tanhf(r.x + A0.x * i0 + A1.x * i1);
            sx[w][col + 1] = tanhf(r.y + A0.y * i0 + A1.y * i1);
            sx[w][col + 2] = tanhf(r.z + A0.z * i0 + A1.z * i1);
            sx[w][col + 3] = tanhf(r.w + A0.w * i0 + A1.w * i1);
        }
    }
    __syncthreads();
    // dense3: 8 nodes x 32 outputs = 256 outputs, one per thread; hrA16 32-wide
    {
        int ln3 = tid >> 5, o3 = tid & 31;
        int nn = blockIdx.x * 8 + ln3;
        float a0 = 0.f, a1 = 0.f, ar = 0.f;
#pragma unroll 8
        for (int i = 0; i < 64; i++) {
            float xv = sx[ln3][i];
            a0 += xv * g_Wl3[i * 32 + o3];
            a1 += xv * g_Wl3[64 * 32 + i * 32 + o3];
            ar += xv * root3[i * 32 + o3];
        }
        g_hrA16[nn * 32 + o3] = __float2half(a0);
        g_hrA16[NN * 32 + nn * 32 + o3] = __float2half(a1);
        g_rootout3[nn * 32 + o3] = ar + rbias3[o3];
    }
}

// ---------------- kernel 7: agg3 (quad-edge quarter-warps) + GAT h GEMM + asv/adv ----------
__global__ void agg3_gath_kernel(const float* __restrict__ gw,
                                 const float* __restrict__ as, const float* __restrict__ ad) {
    __shared__ __align__(16) float sx[16][32];
    __shared__ float s_as[16], s_ad[16];
    int tid = threadIdx.x;  // 512
    int node0 = blockIdx.x * 16;
    int w = tid >> 5, lane = tid & 31;
    int hl = lane & 7, side = lane >> 3;
    {
        int node = node0 + w;
        int beg = g_rowptr[node], end = g_rowptr[node + 1];
        float4 A0 = make_float4(0.f, 0.f, 0.f, 0.f), A1 = A0;
        float C0 = 0.f, C1 = 0.f;
        agg32_quad((const uint2*)g_hrA16, beg, end, hl, side, A0, A1, C0, C1);
        if (side == 0) {
            int col = hl * 4;
            float i0 = 1.f / fmaxf(C0, 1.f), i1 = 1.f / fmaxf(C1, 1.f);
            float4 r = *(const float4*)(g_rootout3 + node * 32 + col);
            sx[w][col + 0] = tanhf(r.x + A0.x * i0 + A1.x * i1);
            sx[w][col + 1] = tanhf(r.y + A0.y * i0 + A1.y * i1);
            sx[w][col + 2] = tanhf(r.z + A0.z * i0 + A1.z * i1);
            sx[w][col + 3] = tanhf(r.w + A0.w * i0 + A1.w * i1);
        }
    }
    if (tid < 16) { s_as[tid] = 0.f; s_ad[tid] = 0.f; }
    __syncthreads();
    // phase 1: GEMM 32 -> 512 with fused attention-logit dots
    int cg = tid & 127;
    int ng = tid >> 7;
    int col4 = cg * 4;
    int nbase = ng * 4;
    float acc[4][4];
#pragma unroll
    for (int a = 0; a < 4; a++)
#pragma unroll
        for (int b = 0; b < 4; b++) acc[a][b] = 0.f;
#pragma unroll 8
    for (int i = 0; i < 32; i++) {
        float4 wv = *(const float4*)(gw + i * 512 + col4);
        float x0 = sx[nbase + 0][i], x1 = sx[nbase + 1][i];
        float x2 = sx[nbase + 2][i], x3 = sx[nbase + 3][i];
        acc[0][0] += x0 * wv.x; acc[0][1] += x0 * wv.y; acc[0][2] += x0 * wv.z; acc[0][3] += x0 * wv.w;
        acc[1][0] += x1 * wv.x; acc[1][1] += x1 * wv.y; acc[1][2] += x1 * wv.z; acc[1][3] += x1 * wv.w;
        acc[2][0] += x2 * wv.x; acc[2][1] += x2 * wv.y; acc[2][2] += x2 * wv.z; acc[2][3] += x2 * wv.w;
        acc[3][0] += x3 * wv.x; acc[3][1] += x3 * wv.y; acc[3][2] += x3 * wv.z; acc[3][3] += x3 * wv.w;
    }
#pragma unroll
    for (int a = 0; a < 4; a++) {
        int nn = node0 + nbase + a;
        __half2 h0 = __floats2half2_rn(acc[a][0], acc[a][1]);
        __half2 h1 = __floats2half2_rn(acc[a][2], acc[a][3]);
        uint2 u;
        u.x = *reinterpret_cast<unsigned*>(&h0);
        u.y = *reinterpret_cast<unsigned*>(&h1);
        *reinterpret_cast<uint2*>(g_hh + (size_t)nn * 512 + col4) = u;
    }
    float4 av = *(const float4*)(as + col4);
    float4 dv = *(const float4*)(ad + col4);
#pragma unroll
    for (int a = 0; a < 4; a++) {
        float ps = acc[a][0] * av.x + acc[a][1] * av.y + acc[a][2] * av.z + acc[a][3] * av.w;
        float pd = acc[a][0] * dv.x + acc[a][1] * dv.y + acc[a][2] * dv.z + acc[a][3] * dv.w;
#pragma unroll
        for (int off = 16; off; off >>= 1) {
            ps += __shfl_down_sync(0xffffffffu, ps, off);
            pd += __shfl_down_sync(0xffffffffu, pd, off);
        }
        if (lane == 0) {
            atomicAdd(&s_as[nbase + a], ps);
            atomicAdd(&s_ad[nbase + a], pd);
        }
    }
    __syncthreads();
    if (tid < 16) {
        int nn = node0 + tid;
        g_asv[nn] = s_as[tid];
        g_adv[nn] = s_ad[tid];
    }
}

// ---------------- kernel 8: GAT softmax-agg -> fp16 node features ----------------
__global__ void gatagg_kernel(const float* __restrict__ gbias) {
    __shared__ float sex[2][64];
    __shared__ int ssrc[2][64];
    int tid = threadIdx.x;
    int node0 = blockIdx.x * 16;
    int g = tid >> 7;
    int gtid = tid & 127;
    const uint2* h2 = (const uint2*)g_hh;   // 4 halves per uint2
    float4 gb4 = ((const float4*)gbias)[gtid];
    for (int k = 0; k < 8; k++) {
        int n = node0 + g * 8 + k;
        int beg = g_rowptr[n], deg = g_rowptr[n + 1] - beg;
        float advn = g_adv[n];
        float exself = expf(lrelu(g_asv[n] + advn));
        float4 hs = ldh4(h2, (size_t)n * 128 + gtid);
        float ax = exself * hs.x, ay = exself * hs.y, az = exself * hs.z, aw = exself * hs.w;
        float dsum = exself;
        for (int base = 0; base < deg; base += 64) {
            int cnt = min(64, deg - base);
            if (gtid < cnt) {
                int v = g_es[beg + base + gtid];
                int s = ES_S(v);
                ssrc[g][gtid] = s;
                sex[g][gtid] = expf(lrelu(g_asv[s] + advn));
            }
            asm volatile("bar.sync %0, %1;" :: "r"(g + 1), "r"(128) : "memory");
            for (int j = 0; j < cnt; j++) {
                float exv = sex[g][j];
                float4 hv = ldh4(h2, (size_t)ssrc[g][j] * 128 + gtid);
                ax += exv * hv.x; ay += exv * hv.y; az += exv * hv.z; aw += exv * hv.w;
                dsum += exv;
            }
            asm volatile("bar.sync %0, %1;" :: "r"(g + 1), "r"(128) : "memory");
        }
        float inv = 1.f / fmaxf(dsum, 1e-16f);
        float ox = fmaxf(ax * inv + gb4.x, 0.f);
        float oy = fmaxf(ay * inv + gb4.y, 0.f);
        float oz = fmaxf(az * inv + gb4.z, 0.f);
        float ow = fmaxf(aw * inv + gb4.w, 0.f);
        __half2 p0 = __floats2half2_rn(ox, oy);
        __half2 p1 = __floats2half2_rn(oz, ow);
        uint2 u;
        u.x = *reinterpret_cast<unsigned*>(&p0);
        u.y = *reinterpret_cast<unsigned*>(&p1);
        *reinterpret_cast<uint2*>(g_x16 + (size_t)n * 512 + gtid * 4) = u;
    }
}

// ---------------- kernel 9: pt/pb GEMM via tensor cores (m16n8k16 fp16/fp32) ----------------
#define MT 32
__global__ void ptpb_mma_kernel(const float* __restrict__ b1) {
    __shared__ __align__(16) __half As[MT][72];
    __shared__ __align__(16) __half Bs[128][72];
    int tid = threadIdx.x;
    int node0 = blockIdx.x * MT;
    int nblk = blockIdx.y;
    int w = tid >> 5, lane = tid & 31;
    int wm = (w >> 2) * 16;
    int wn = (w & 3) * 32;
    int grp = lane >> 2, tig = lane & 3;
    float acc[4][4];
#pragma unroll
    for (int a = 0; a < 4; a++)
#pragma unroll
        for (int b = 0; b < 4; b++) acc[a][b] = 0.f;
    const __half* wT = g_w1hT + (size_t)nblk * 128 * 512;
#pragma unroll 1
    for (int kt = 0; kt < 8; kt++) {
        int k0 = kt * 64;
        {
            int m = tid >> 3, kc = (tid & 7) * 8;
            int node = node0 + m;
            uint4 v = make_uint4(0u, 0u, 0u, 0u);
            if (node < NN) v = *(const uint4*)(g_x16 + (size_t)node * 512 + k0 + kc);
            *(uint4*)&As[m][kc] = v;
        }
        {
            int n = tid >> 1, kc = (tid & 1) * 32;
            const __half* src = wT + (size_t)n * 512 + k0 + kc;
            uint4 v0 = ((const uint4*)src)[0];
            uint4 v1 = ((const uint4*)src)[1];
            uint4 v2 = ((const uint4*)src)[2];
            uint4 v3 = ((const uint4*)src)[3];
            *(uint4*)&Bs[n][kc] = v0;
            *(uint4*)&Bs[n][kc + 8] = v1;
            *(uint4*)&Bs[n][kc + 16] = v2;
            *(uint4*)&Bs[n][kc + 24] = v3;
        }
        __syncthreads();
#pragma unroll
        for (int ks = 0; ks < 4; ks++) {
            int kk = ks * 16 + tig * 2;
            unsigned a0 = *(const unsigned*)&As[wm + grp][kk];
            unsigned a1 = *(const unsigned*)&As[wm + grp + 8][kk];
            unsigned a2 = *(const unsigned*)&As[wm + grp][kk + 8];
            unsigned a3 = *(const unsigned*)&As[wm + grp + 8][kk + 8];
#pragma unroll
            for (int nf = 0; nf < 4; nf++) {
                int n8 = wn + nf * 8 + grp;
                unsigned b0 = *(const unsigned*)&Bs[n8][kk];
                unsigned b1r = *(const unsigned*)&Bs[n8][kk + 8];
                asm volatile(
                    "mma.sync.aligned.m16n8k16.row.col.f32.f16.f16.f32 "
                    "{%0,%1,%2,%3}, {%4,%5,%6,%7}, {%8,%9}, {%0,%1,%2,%3};"
                    : "+f"(acc[nf][0]), "+f"(acc[nf][1]), "+f"(acc[nf][2]), "+f"(acc[nf][3])
                    : "r"(a0), "r"(a1), "r"(a2), "r"(a3), "r"(b0), "r"(b1r));
            }
        }
        __syncthreads();
    }
#pragma unroll
    for (int nf = 0; nf < 4; nf++) {
        int ncol = nblk * 128 + wn + nf * 8 + tig * 2;   // global col 0..255
        float bx_ = 0.f, by_ = 0.f;
        float* obase;
        int oc;
        if (ncol < 128) {
            obase = g_pt; oc = ncol;
            float2 bb = *(const float2*)(b1 + ncol);
            bx_ = bb.x; by_ = bb.y;
        } else {
            obase = g_pb; oc = ncol - 128;
        }
        int n0 = node0 + wm + grp;
        if (n0 < NN)
            *(float2*)(obase + (size_t)n0 * 128 + oc) = make_float2(acc[nf][0] + bx_, acc[nf][1] + by_);
        int n1 = n0 + 8;
        if (n1 < NN)
            *(float2*)(obase + (size_t)n1 * 128 + oc) = make_float2(acc[nf][2] + bx_, acc[nf][3] + by_);
    }
}

// ---------------- kernel 10: per-edge output, CSR order (pb[dst] loaded once/warp) ----------------
__global__ void edge_out_kernel(const float* __restrict__ w2, const float* __restrict__ b2,
                                float* __restrict__ out) {
    int tid = threadIdx.x, w = tid >> 5, lane = tid & 31;
    int node = blockIdx.x * 8 + w;
    int beg = g_rowptr[node], end = g_rowptr[node + 1];
    if (beg == end) return;
    const float4* pt4 = (const float4*)g_pt;
    float4 pbv = ((const float4*)g_pb)[(size_t)node * 32 + lane];
    float4 wv = ((const float4*)w2)[lane];
    float bias = b2[0];
    int k = beg;
    for (; k + 2 <= end; k += 2) {
        int v0 = g_es[k], v1 = g_es[k + 1];
        float4 a0 = pt4[(size_t)ES_S(v0) * 32 + lane];
        float4 a1 = pt4[(size_t)ES_S(v1) * 32 + lane];
        float r0 = fmaxf(a0.x + pbv.x, 0.f) * wv.x + fmaxf(a0.y + pbv.y, 0.f) * wv.y
                 + fmaxf(a0.z + pbv.z, 0.f) * wv.z + fmaxf(a0.w + pbv.w, 0.f) * wv.w;
        float r1 = fmaxf(a1.x + pbv.x, 0.f) * wv.x + fmaxf(a1.y + pbv.y, 0.f) * wv.y
                 + fmaxf(a1.z + pbv.z, 0.f) * wv.z + fmaxf(a1.w + pbv.w, 0.f) * wv.w;
#pragma unroll
        for (int off = 16; off; off >>= 1) {
            r0 += __shfl_down_sync(0xffffffffu, r0, off);
            r1 += __shfl_down_sync(0xffffffffu, r1, off);
        }
        if (lane == 0) {
            out[ES_E(v0)] = 1.f / (1.f + expf(-(r0 + bias)));
            out[ES_E(v1)] = 1.f / (1.f + expf(-(r1 + bias)));
        }
    }
    if (k < end) {
        int v = g_es[k];
        float4 a = pt4[(size_t)ES_S(v) * 32 + lane];
        float r = fmaxf(a.x + pbv.x, 0.f) * wv.x + fmaxf(a.y + pbv.y, 0.f) * wv.y
                + fmaxf(a.z + pbv.z, 0.f) * wv.z + fmaxf(a.w + pbv.w, 0.f) * wv.w;
#pragma unroll
        for (int off = 16; off; off >>= 1) r += __shfl_down_sync(0xffffffffu, r, off);
        if (lane == 0) out[ES_E(v)] = 1.f / (1.f + expf(-(r + bias)));
    }
}

// ---------------- launch ----------------
extern "C" void kernel_launch(void* const* d_in, const int* in_sizes, int n_in,
                              void* d_out, int out_size) {
    int off, iE, iT;
    if (in_sizes[0] == 2 * EE) { off = 2; iE = 0; iT = 1; }
    else                       { off = 0; iE = 24; iT = 25; }
    const int* ei = (const int*)d_in[iE];
    const int* et = (const int*)d_in[iT];
    const int* src = ei;
    const int* dst = ei + EE;
    const float* basis0 = (const float*)d_in[off + 0];
    const float* comp0  = (const float*)d_in[off + 1];
    const float* root0  = (const float*)d_in[off + 2];
    const float* rbias0 = (const float*)d_in[off + 3];
    const float* basis1 = (const float*)d_in[off + 4];
    const float* comp1  = (const float*)d_in[off + 5];
    const float* root1  = (const float*)d_in[off + 6];
    const float* rbias1 = (const float*)d_in[off + 7];
    const float* basis2 = (const float*)d_in[off + 8];
    const float* comp2  = (const float*)d_in[off + 9];
    const float* root2  = (const float*)d_in[off + 10];
    const float* rbias2 = (const float*)d_in[off + 11];
    const float* basis3 = (const float*)d_in[off + 12];
    const float* comp3  = (const float*)d_in[off + 13];
    const float* root3  = (const float*)d_in[off + 14];
    const float* rbias3 = (const float*)d_in[off + 15];
    const float* gw  = (const float*)d_in[off + 16];
    const float* gas = (const float*)d_in[off + 17];
    const float* gad = (const float*)d_in[off + 18];
    const float* gb  = (const float*)d_in[off + 19];
    const float* w1  = (const float*)d_in[off + 20];
    const float* b1  = (const float*)d_in[off + 21];
    const float* w2  = (const float*)d_in[off + 22];
    const float* b2  = (const float*)d_in[off + 23];
    float* out = (float*)d_out;

    pre_count_kernel<<<PRE_BLOCKS + CNT_BLOCKS + W1H_BLOCKS, 256>>>(
        basis0, comp0, basis1, comp1, basis2, comp2, basis3, comp3, dst, w1);
    scan_kernel<<<1, 1024>>>();
    scatter_kernel<<<CNT_BLOCKS, 256>>>(src, dst, et);

    l0d1_kernel<<<NN / 8, 256>>>(root0, rbias0, root1, rbias1);
    a1d2_kernel<<<NN / 8, 256>>>(root2, rbias2);
    a2d3_kernel<<<NN / 8, 256>>>(root3, rbias3);

    agg3_gath_kernel<<<NN / 16, 512>>>(gw, gas, gad);
    gatagg_kernel<<<NN / 16, 256>>>(gb);
    {
        dim3 grid((NN + MT - 1) / MT, 2);
        ptpb_mma_kernel<<<grid, 256>>>(b1);
    }
    edge_out_kernel<<<NN / 8, 256>>>(w2, b2, out);
}

// round 16
// speedup vs baseline: 1.1133x; 1.0373x over previous
#include <cuda_runtime.h>
#include <cuda_fp16.h>
#include <math.h>

#define NN 6000
#define EE 100000

#if defined(__CUDA_ARCH__) && __CUDA_ARCH__ >= 900
#define GRID_DEP_SYNC() cudaGridDependencySynchronize()
#else
#define GRID_DEP_SYNC()
#endif

// ---------------- device scratch (static, no allocation) ----------------
__device__ int g_deg[NN];          // zeroed at end of scan_kernel each launch (starts zeroed)
__device__ int g_rowptr[NN + 1];
__device__ int g_rank[EE];
__device__ int g_es[EE];           // packed per CSR slot: e | (src<<17) | (type<<30)

__device__ __align__(16) __half g_W0h[2 * NN * 32];  // layer-0 relation weights, fp16
__device__ __align__(16) float g_Wl1[2 * 32 * 64];
__device__ __align__(16) float g_Wl2[2 * 64 * 64];
__device__ __align__(16) float g_Wl3[2 * 64 * 32];
__device__ __align__(16) __half g_hrA16[2 * NN * 64];  // layers 1 (64-wide) / 3 (32-wide), fp16
__device__ __align__(16) __half g_hrB16[2 * NN * 64];  // layer 2 (64-wide), fp16
__device__ __align__(16) float g_rootout[NN * 64];
__device__ __align__(16) float g_rootout3[NN * 32];
__device__ __align__(16) __half g_hh[NN * 512];      // GAT hidden (fp16)
__device__ float g_asv[NN], g_adv[NN];
__device__ __align__(16) __half g_x16[NN * 512];     // GAT output features (fp16, GEMM A)
__device__ __align__(16) __half g_w1hT[256 * 512];   // w1 fp16, transposed [out][k]
__device__ __align__(16) float g_pt[NN * 128];       // x @ w1[0:512] (+ b1)
__device__ __align__(16) float g_pb[NN * 128];       // x @ w1[512:1024]

__device__ __forceinline__ float lrelu(float v) { return v > 0.f ? v : 0.2f * v; }

// load 4 consecutive halves as float4
__device__ __forceinline__ float4 ldh4(const uint2* base, size_t idx) {
    uint2 u = base[idx];
    __half2 p0 = *reinterpret_cast<__half2*>(&u.x);
    __half2 p1 = *reinterpret_cast<__half2*>(&u.y);
    float2 f0 = __half22float2(p0);
    float2 f1 = __half22float2(p1);
    return make_float4(f0.x, f0.y, f1.x, f1.y);
}

// ---------------- kernel 1: relation-weight precompute + degree count + w1->fp16T ----------------
#define W0_CNT (2 * NN * 32)
#define WL1_CNT (2 * 32 * 64)
#define WL2_CNT (2 * 64 * 64)
#define WL3_CNT (2 * 64 * 32)
#define PRE_CNT (W0_CNT + WL1_CNT + WL2_CNT + WL3_CNT)
#define PRE_BLOCKS (PRE_CNT / 256)              // exact
#define CNT_BLOCKS ((EE + 255) / 256)
#define W1H_BLOCKS ((256 * 512) / 256)          // 512

__global__ void pre_count_kernel(const float* __restrict__ basis0, const float* __restrict__ comp0,
                                 const float* __restrict__ basis1, const float* __restrict__ comp1,
                                 const float* __restrict__ basis2, const float* __restrict__ comp2,
                                 const float* __restrict__ basis3, const float* __restrict__ comp3,
                                 const int* __restrict__ dst, const float* __restrict__ w1) {
    GRID_DEP_SYNC();
    int bid = blockIdx.x;
    if (bid >= PRE_BLOCKS + CNT_BLOCKS) {
        // w1 -> fp16 transposed, load-coalesced mapping: consecutive threads
        // take consecutive output rows o (same k index i), so the w1 reads
        // within a warp are contiguous.
        int idx = (bid - PRE_BLOCKS - CNT_BLOCKS) * 256 + threadIdx.x;
        int o = idx & 255, i = idx >> 8;
        g_w1hT[o * 512 + i] = __float2half(w1[(i + ((o >= 128) ? 512 : 0)) * 128 + (o & 127)]);
        return;
    }
    if (bid >= PRE_BLOCKS) {
        int e = (bid - PRE_BLOCKS) * 256 + threadIdx.x;
        if (e < EE) g_rank[e] = atomicAdd(&g_deg[dst[e]], 1);
        return;
    }
    int idx = bid * 256 + threadIdx.x;
    if (idx < W0_CNT) {
        int per = NN * 32;
        int r = idx / per, rem = idx - r * per;
        float v = 0.f;
#pragma unroll
        for (int b = 0; b < 4; b++) v += comp0[r * 4 + b] * basis0[b * per + rem];
        g_W0h[idx] = __float2half(v);
        return;
    }
    idx -= W0_CNT;
    if (idx < WL1_CNT) {
        int per = 32 * 64;
        int r = idx / per, rem = idx - r * per;
        float v = 0.f;
#pragma unroll
        for (int b = 0; b < 4; b++) v += comp1[r * 4 + b] * basis1[b * per + rem];
        g_Wl1[idx] = v;
        return;
    }
    idx -= WL1_CNT;
    if (idx < WL2_CNT) {
        int per = 64 * 64;
        int r = idx / per, rem = idx - r * per;
        float v = 0.f;
#pragma unroll
        for (int b = 0; b < 4; b++) v += comp2[r * 4 + b] * basis2[b * per + rem];
        g_Wl2[idx] = v;
        return;
    }
    idx -= WL2_CNT;
    {
        int per = 64 * 32;
        int r = idx / per, rem = idx - r * per;
        float v = 0.f;
#pragma unroll
        for (int b = 0; b < 4; b++) v += comp3[r * 4 + b] * basis3[b * per + rem];
        g_Wl3[idx] = v;
    }
}

// ---------------- kernel 2: single-pass scan (also re-zeroes deg for next launch) ----------------
__global__ void scan_kernel() {
    GRID_DEP_SYNC();
    __shared__ int swsum[32];
    int tid = threadIdx.x, lane = tid & 31, wid = tid >> 5;
    int base = tid * 6;
    int v[6];
    int s = 0;
#pragma unroll
    for (int j = 0; j < 6; j++) {
        int i = base + j;
        v[j] = (i < NN) ? g_deg[i] : 0;
        s += v[j];
    }
    int x = s;
#pragma unroll
    for (int off = 1; off < 32; off <<= 1) {
        int t = __shfl_up_sync(0xffffffffu, x, off);
        if (lane >= off) x += t;
    }
    if (lane == 31) swsum[wid] = x;
    __syncthreads();
    if (wid == 0) {
        int y = swsum[lane];
#pragma unroll
        for (int off = 1; off < 32; off <<= 1) {
            int t = __shfl_up_sync(0xffffffffu, y, off);
            if (lane >= off) y += t;
        }
        swsum[lane] = y;
    }
    __syncthreads();
    int run = x - s + (wid ? swsum[wid - 1] : 0);
#pragma unroll
    for (int j = 0; j < 6; j++) {
        int i = base + j;
        run += v[j];
        if (i < NN) g_rowptr[i + 1] = run;
    }
    if (tid == 0) g_rowptr[0] = 0;
#pragma unroll
    for (int j = 0; j < 6; j++) {
        int i = base + j;
        if (i < NN) g_deg[i] = 0;   // restore invariant for next launch
    }
}

// ---------------- kernel 3: atomic-free scatter, packed slot ----------------
__global__ void scatter_kernel(const int* __restrict__ src, const int* __restrict__ dst,
                               const int* __restrict__ et) {
    GRID_DEP_SYNC();
    int e = blockIdx.x * blockDim.x + threadIdx.x;
    if (e < EE) {
        int p = g_rowptr[dst[e]] + g_rank[e];
        g_es[p] = e | (src[e] << 17) | (et[e] << 30);
    }
}

#define ES_S(v) (((v) >> 17) & 0x1FFF)
#define ES_T(v) (((v) >> 30) & 1)
#define ES_E(v) ((v) & 0x1FFFF)

// quad-edge quarter-warp 32-wide fp16 aggregation
__device__ __forceinline__ void agg32_quad(const uint2* rows, int beg, int end,
                                           int hl, int side,
                                           float4& A0, float4& A1, float& C0, float& C1) {
    int k = beg + side;
    for (; k + 4 < end; k += 8) {
        int v0 = g_es[k], v1 = g_es[k + 4];
        float4 f0 = ldh4(rows, (size_t)(ES_T(v0) * NN + ES_S(v0)) * 8 + hl);
        float4 f1 = ldh4(rows, (size_t)(ES_T(v1) * NN + ES_S(v1)) * 8 + hl);
        if (ES_T(v0)) { A1.x += f0.x; A1.y += f0.y; A1.z += f0.z; A1.w += f0.w; C1 += 1.f; }
        else          { A0.x += f0.x; A0.y += f0.y; A0.z += f0.z; A0.w += f0.w; C0 += 1.f; }
        if (ES_T(v1)) { A1.x += f1.x; A1.y += f1.y; A1.z += f1.z; A1.w += f1.w; C1 += 1.f; }
        else          { A0.x += f1.x; A0.y += f1.y; A0.z += f1.z; A0.w += f1.w; C0 += 1.f; }
    }
    if (k < end) {
        int v = g_es[k];
        float4 f = ldh4(rows, (size_t)(ES_T(v) * NN + ES_S(v)) * 8 + hl);
        if (ES_T(v)) { A1.x += f.x; A1.y += f.y; A1.z += f.z; A1.w += f.w; C1 += 1.f; }
        else         { A0.x += f.x; A0.y += f.y; A0.z += f.z; A0.w += f.w; C0 += 1.f; }
    }
#pragma unroll
    for (int off = 8; off <= 16; off <<= 1) {
        A0.x += __shfl_xor_sync(0xffffffffu, A0.x, off);
        A0.y += __shfl_xor_sync(0xffffffffu, A0.y, off);
        A0.z += __shfl_xor_sync(0xffffffffu, A0.z, off);
        A0.w += __shfl_xor_sync(0xffffffffu, A0.w, off);
        A1.x += __shfl_xor_sync(0xffffffffu, A1.x, off);
        A1.y += __shfl_xor_sync(0xffffffffu, A1.y, off);
        A1.z += __shfl_xor_sync(0xffffffffu, A1.z, off);
        A1.w += __shfl_xor_sync(0xffffffffu, A1.w, off);
        C0 += __shfl_xor_sync(0xffffffffu, C0, off);
        C1 += __shfl_xor_sync(0xffffffffu, C1, off);
    }
}

// dual-edge half-warp 64-wide fp16 aggregation
__device__ __forceinline__ void agg64_dual(const uint2* rows, int beg, int end,
                                           int hl, int side,
                                           float4& A0, float4& A1, float& C0, float& C1) {
    int k = beg + side;
    for (; k + 2 < end; k += 4) {
        int v0 = g_es[k], v1 = g_es[k + 2];
        float4 f0 = ldh4(rows, (size_t)(ES_T(v0) * NN + ES_S(v0)) * 16 + hl);
        float4 f1 = ldh4(rows, (size_t)(ES_T(v1) * NN + ES_S(v1)) * 16 + hl);
        if (ES_T(v0)) { A1.x += f0.x; A1.y += f0.y; A1.z += f0.z; A1.w += f0.w; C1 += 1.f; }
        else          { A0.x += f0.x; A0.y += f0.y; A0.z += f0.z; A0.w += f0.w; C0 += 1.f; }
        if (ES_T(v1)) { A1.x += f1.x; A1.y += f1.y; A1.z += f1.z; A1.w += f1.w; C1 += 1.f; }
        else          { A0.x += f1.x; A0.y += f1.y; A0.z += f1.z; A0.w += f1.w; C0 += 1.f; }
    }
    if (k < end) {
        int v = g_es[k];
        float4 f = ldh4(rows, (size_t)(ES_T(v) * NN + ES_S(v)) * 16 + hl);
        if (ES_T(v)) { A1.x += f.x; A1.y += f.y; A1.z += f.z; A1.w += f.w; C1 += 1.f; }
        else         { A0.x += f.x; A0.y += f.y; A0.z += f.z; A0.w += f.w; C0 += 1.f; }
    }
    A0.x += __shfl_xor_sync(0xffffffffu, A0.x, 16);
    A0.y += __shfl_xor_sync(0xffffffffu, A0.y, 16);
    A0.z += __shfl_xor_sync(0xffffffffu, A0.z, 16);
    A0.w += __shfl_xor_sync(0xffffffffu, A0.w, 16);
    A1.x += __shfl_xor_sync(0xffffffffu, A1.x, 16);
    A1.y += __shfl_xor_sync(0xffffffffu, A1.y, 16);
    A1.z += __shfl_xor_sync(0xffffffffu, A1.z, 16);
    A1.w += __shfl_xor_sync(0xffffffffu, A1.w, 16);
    C0 += __shfl_xor_sync(0xffffffffu, C0, 16);
    C1 += __shfl_xor_sync(0xffffffffu, C1, 16);
}

// ---------------- kernel 4: layer-0 agg (quad-edge quarter-warps) + dense1 fused ----------
__global__ void l0d1_kernel(const float* __restrict__ root0, const float* __restrict__ rbias0,
                            const float* __restrict__ root1, const float* __restrict__ rbias1) {
    GRID_DEP_SYNC();
    __shared__ __align__(16) float sx[8][32];
    int tid = threadIdx.x, w = tid >> 5, lane = tid & 31;
    int hl = lane & 7, side = lane >> 3;
    int node = blockIdx.x * 8 + w;
    {
        int beg = g_rowptr[node], end = g_rowptr[node + 1];
        float4 A0 = make_float4(0.f, 0.f, 0.f, 0.f), A1 = A0;
        float C0 = 0.f, C1 = 0.f;
        agg32_quad((const uint2*)g_W0h, beg, end, hl, side, A0, A1, C0, C1);
        if (side == 0) {
            int col = hl * 4;
            float i0 = 1.f / fmaxf(C0, 1.f), i1 = 1.f / fmaxf(C1, 1.f);
            float4 r = *(const float4*)(root0 + node * 32 + col);
            float4 rb = *(const float4*)(rbias0 + col);
            sx[w][col + 0] = tanhf(r.x + rb.x + A0.x * i0 + A1.x * i1);
            sx[w][col + 1] = tanhf(r.y + rb.y + A0.y * i0 + A1.y * i1);
            sx[w][col + 2] = tanhf(r.z + rb.z + A0.z * i0 + A1.z * i1);
            sx[w][col + 3] = tanhf(r.w + rb.w + A0.w * i0 + A1.w * i1);
        }
    }
    __syncthreads();
#pragma unroll
    for (int t = tid; t < 512; t += 256) {
        int ln = t >> 6, o = t & 63;
        int nn = blockIdx.x * 8 + ln;
        float a0 = 0.f, a1 = 0.f, ar = 0.f;
#pragma unroll 8
        for (int i = 0; i < 32; i++) {
            float xv = sx[ln][i];
            a0 += xv * g_Wl1[i * 64 + o];
            a1 += xv * g_Wl1[32 * 64 + i * 64 + o];
            ar += xv * root1[i * 64 + o];
        }
        g_hrA16[nn * 64 + o] = __float2half(a0);
        g_hrA16[NN * 64 + nn * 64 + o] = __float2half(a1);
        g_rootout[nn * 64 + o] = ar + rbias1[o];
    }
}

// ---------------- kernel 5: agg1 (dual-edge half-warps) + dense2 fused ----------------
__global__ void a1d2_kernel(const float* __restrict__ root2, const float* __restrict__ rbias2) {
    GRID_DEP_SYNC();
    __shared__ __align__(16) float sx[8][64];
    int tid = threadIdx.x, w = tid >> 5, lane = tid & 31;
    int hl = lane & 15, side = lane >> 4;
    int node = blockIdx.x * 8 + w;
    {
        int beg = g_rowptr[node], end = g_rowptr[node + 1];
        float4 A0 = make_float4(0.f, 0.f, 0.f, 0.f), A1 = A0;
        float C0 = 0.f, C1 = 0.f;
        agg64_dual((const uint2*)g_hrA16, beg, end, hl, side, A0, A1, C0, C1);
        if (side == 0) {
            int col = hl * 4;
            float i0 = 1.f / fmaxf(C0, 1.f), i1 = 1.f / fmaxf(C1, 1.f);
            float4 r = *(const float4*)(g_rootout + node * 64 + col);
            sx[w][col + 0] = tanhf(r.x + A0.x * i0 + A1.x * i1);
            sx[w][col + 1] = tanhf(r.y + A0.y * i0 + A1.y * i1);
            sx[w][col + 2] = tanhf(r.z + A0.z * i0 + A1.z * i1);
            sx[w][col + 3] = tanhf(r.w + A0.w * i0 + A1.w * i1);
        }
    }
    __syncthreads();
#pragma unroll
    for (int t = tid; t < 512; t += 256) {
        int ln = t >> 6, o = t & 63;
        int nn = blockIdx.x * 8 + ln;
        float a0 = 0.f, a1 = 0.f, ar = 0.f;
#pragma unroll 8
        for (int i = 0; i < 64; i++) {
            float xv = sx[ln][i];
            a0 += xv * g_Wl2[i * 64 + o];
            a1 += xv * g_Wl2[64 * 64 + i * 64 + o];
            ar += xv * root2[i * 64 + o];
        }
        g_hrB16[nn * 64 + o] = __float2half(a0);
        g_hrB16[NN * 64 + nn * 64 + o] = __float2half(a1);
        g_rootout[nn * 64 + o] = ar + rbias2[o];
    }
}

// ---------------- kernel 6: agg2 (dual-edge half-warps) + dense3 fused ----------------
__global__ void a2d3_kernel(const float* __restrict__ root3, const float* __restrict__ rbias3) {
    GRID_DEP_SYNC();
    __shared__ __align__(16) float sx[8][64];
    int tid = threadIdx.x, w = tid >> 5, lane = tid & 31;
    int hl = lane & 15, side = lane >> 4;
    int node = blockIdx.x * 8 + w;
    {
        int beg = g_rowptr[node], end = g_rowptr[node + 1];
        float4 A0 = make_float4(0.f, 0.f, 0.f, 0.f), A1 = A0;
        float C0 = 0.f, C1 = 0.f;
        agg64_dual((const uint2*)g_hrB16, beg, end, hl, side, A0, A1, C0, C1);
        if (side == 0) {
            int col = hl * 4;
            float i0 = 1.f / fmaxf(C0, 1.f), i1 = 1.f / fmaxf(C1, 1.f);
            float4 r = *(const float4*)(g_rootout + node * 64 + col);
            sx[w][col + 0] = tanhf(r.x + A0.x * i0 + A1.x * i1);
            sx[w][col + 1] = tanhf(r.y + A0.y * i0 + A1.y * i1);
            sx[w][col + 2] = tanhf(r.z + A0.z * i0 + A1.z * i1);
            sx[w][col + 3] = tanhf(r.w + A0.w * i0 + A1.w * i1);
        }
    }
    __syncthreads();
    {
        int ln3 = tid >> 5, o3 = tid & 31;
        int nn = blockIdx.x * 8 + ln3;
        float a0 = 0.f, a1 = 0.f, ar = 0.f;
#pragma unroll 8
        for (int i = 0; i < 64; i++) {
            float xv = sx[ln3][i];
            a0 += xv * g_Wl3[i * 32 + o3];
            a1 += xv * g_Wl3[64 * 32 + i * 32 + o3];
            ar += xv * root3[i * 32 + o3];
        }
        g_hrA16[nn * 32 + o3] = __float2half(a0);
        g_hrA16[NN * 32 + nn * 32 + o3] = __float2half(a1);
        g_rootout3[nn * 32 + o3] = ar + rbias3[o3];
    }
}

// ---------------- kernel 7: agg3 (quad-edge quarter-warps) + GAT h GEMM + asv/adv ----------
__global__ void agg3_gath_kernel(const float* __restrict__ gw,
                                 const float* __restrict__ as, const float* __restrict__ ad) {
    GRID_DEP_SYNC();
    __shared__ __align__(16) float sx[16][32];
    __shared__ float s_as[16], s_ad[16];
    int tid = threadIdx.x;  // 512
    int node0 = blockIdx.x * 16;
    int w = tid >> 5, lane = tid & 31;
    int hl = lane & 7, side = lane >> 3;
    {
        int node = node0 + w;
        int beg = g_rowptr[node], end = g_rowptr[node + 1];
        float4 A0 = make_float4(0.f, 0.f, 0.f, 0.f), A1 = A0;
        float C0 = 0.f, C1 = 0.f;
        agg32_quad((const uint2*)g_hrA16, beg, end, hl, side, A0, A1, C0, C1);
        if (side == 0) {
            int col = hl * 4;
            float i0 = 1.f / fmaxf(C0, 1.f), i1 = 1.f / fmaxf(C1, 1.f);
            float4 r = *(const float4*)(g_rootout3 + node * 32 + col);
            sx[w][col + 0] = tanhf(r.x + A0.x * i0 + A1.x * i1);
            sx[w][col + 1] = tanhf(r.y + A0.y * i0 + A1.y * i1);
            sx[w][col + 2] = tanhf(r.z + A0.z * i0 + A1.z * i1);
            sx[w][col + 3] = tanhf(r.w + A0.w * i0 + A1.w * i1);
        }
    }
    if (tid < 16) { s_as[tid] = 0.f; s_ad[tid] = 0.f; }
    __syncthreads();
    int cg = tid & 127;
    int ng = tid >> 7;
    int col4 = cg * 4;
    int nbase = ng * 4;
    float acc[4][4];
#pragma unroll
    for (int a = 0; a < 4; a++)
#pragma unroll
        for (int b = 0; b < 4; b++) acc[a][b] = 0.f;
#pragma unroll 8
    for (int i = 0; i < 32; i++) {
        float4 wv = *(const float4*)(gw + i * 512 + col4);
        float x0 = sx[nbase + 0][i], x1 = sx[nbase + 1][i];
        float x2 = sx[nbase + 2][i], x3 = sx[nbase + 3][i];
        acc[0][0] += x0 * wv.x; acc[0][1] += x0 * wv.y; acc[0][2] += x0 * wv.z; acc[0][3] += x0 * wv.w;
        acc[1][0] += x1 * wv.x; acc[1][1] += x1 * wv.y; acc[1][2] += x1 * wv.z; acc[1][3] += x1 * wv.w;
        acc[2][0] += x2 * wv.x; acc[2][1] += x2 * wv.y; acc[2][2] += x2 * wv.z; acc[2][3] += x2 * wv.w;
        acc[3][0] += x3 * wv.x; acc[3][1] += x3 * wv.y; acc[3][2] += x3 * wv.z; acc[3][3] += x3 * wv.w;
    }
#pragma unroll
    for (int a = 0; a < 4; a++) {
        int nn = node0 + nbase + a;
        __half2 h0 = __floats2half2_rn(acc[a][0], acc[a][1]);
        __half2 h1 = __floats2half2_rn(acc[a][2], acc[a][3]);
        uint2 u;
        u.x = *reinterpret_cast<unsigned*>(&h0);
        u.y = *reinterpret_cast<unsigned*>(&h1);
        *reinterpret_cast<uint2*>(g_hh + (size_t)nn * 512 + col4) = u;
    }
    float4 av = *(const float4*)(as + col4);
    float4 dv = *(const float4*)(ad + col4);
#pragma unroll
    for (int a = 0; a < 4; a++) {
        float ps = acc[a][0] * av.x + acc[a][1] * av.y + acc[a][2] * av.z + acc[a][3] * av.w;
        float pd = acc[a][0] * dv.x + acc[a][1] * dv.y + acc[a][2] * dv.z + acc[a][3] * dv.w;
#pragma unroll
        for (int off = 16; off; off >>= 1) {
            ps += __shfl_down_sync(0xffffffffu, ps, off);
            pd += __shfl_down_sync(0xffffffffu, pd, off);
        }
        if (lane == 0) {
            atomicAdd(&s_as[nbase + a], ps);
            atomicAdd(&s_ad[nbase + a], pd);
        }
    }
    __syncthreads();
    if (tid < 16) {
        int nn = node0 + tid;
        g_asv[nn] = s_as[tid];
        g_adv[nn] = s_ad[tid];
    }
}

// ---------------- kernel 8: GAT softmax-agg -> fp16 node features ----------------
__global__ void gatagg_kernel(const float* __restrict__ gbias) {
    GRID_DEP_SYNC();
    __shared__ float sex[2][64];
    __shared__ int ssrc[2][64];
    int tid = threadIdx.x;
    int node0 = blockIdx.x * 16;
    int g = tid >> 7;
    int gtid = tid & 127;
    const uint2* h2 = (const uint2*)g_hh;   // 4 halves per uint2
    float4 gb4 = ((const float4*)gbias)[gtid];
    for (int k = 0; k < 8; k++) {
        int n = node0 + g * 8 + k;
        int beg = g_rowptr[n], deg = g_rowptr[n + 1] - beg;
        float advn = g_adv[n];
        float exself = expf(lrelu(g_asv[n] + advn));
        float4 hs = ldh4(h2, (size_t)n * 128 + gtid);
        float ax = exself * hs.x, ay = exself * hs.y, az = exself * hs.z, aw = exself * hs.w;
        float dsum = exself;
        for (int base = 0; base < deg; base += 64) {
            int cnt = min(64, deg - base);
            if (gtid < cnt) {
                int v = g_es[beg + base + gtid];
                int s = ES_S(v);
                ssrc[g][gtid] = s;
                sex[g][gtid] = expf(lrelu(g_asv[s] + advn));
            }
            asm volatile("bar.sync %0, %1;" :: "r"(g + 1), "r"(128) : "memory");
            for (int j = 0; j < cnt; j++) {
                float exv = sex[g][j];
                float4 hv = ldh4(h2, (size_t)ssrc[g][j] * 128 + gtid);
                ax += exv * hv.x; ay += exv * hv.y; az += exv * hv.z; aw += exv * hv.w;
                dsum += exv;
            }
            asm volatile("bar.sync %0, %1;" :: "r"(g + 1), "r"(128) : "memory");
        }
        float inv = 1.f / fmaxf(dsum, 1e-16f);
        float ox = fmaxf(ax * inv + gb4.x, 0.f);
        float oy = fmaxf(ay * inv + gb4.y, 0.f);
        float oz = fmaxf(az * inv + gb4.z, 0.f);
        float ow = fmaxf(aw * inv + gb4.w, 0.f);
        __half2 p0 = __floats2half2_rn(ox, oy);
        __half2 p1 = __floats2half2_rn(oz, ow);
        uint2 u;
        u.x = *reinterpret_cast<unsigned*>(&p0);
        u.y = *reinterpret_cast<unsigned*>(&p1);
        *reinterpret_cast<uint2*>(g_x16 + (size_t)n * 512 + gtid * 4) = u;
    }
}

// ---------------- kernel 9: pt/pb GEMM via tensor cores (m16n8k16 fp16/fp32) ----------------
#define MT 32
__global__ void ptpb_mma_kernel(const float* __restrict__ b1) {
    GRID_DEP_SYNC();
    __shared__ __align__(16) __half As[MT][72];
    __shared__ __align__(16) __half Bs[128][72];
    int tid = threadIdx.x;
    int node0 = blockIdx.x * MT;
    int nblk = blockIdx.y;
    int w = tid >> 5, lane = tid & 31;
    int wm = (w >> 2) * 16;
    int wn = (w & 3) * 32;
    int grp = lane >> 2, tig = lane & 3;
    float acc[4][4];
#pragma unroll
    for (int a = 0; a < 4; a++)
#pragma unroll
        for (int b = 0; b < 4; b++) acc[a][b] = 0.f;
    const __half* wT = g_w1hT + (size_t)nblk * 128 * 512;
#pragma unroll 1
    for (int kt = 0; kt < 8; kt++) {
        int k0 = kt * 64;
        {
            int m = tid >> 3, kc = (tid & 7) * 8;
            int node = node0 + m;
            uint4 v = make_uint4(0u, 0u, 0u, 0u);
            if (node < NN) v = *(const uint4*)(g_x16 + (size_t)node * 512 + k0 + kc);
            *(uint4*)&As[m][kc] = v;
        }
        {
            int n = tid >> 1, kc = (tid & 1) * 32;
            const __half* src = wT + (size_t)n * 512 + k0 + kc;
            uint4 v0 = ((const uint4*)src)[0];
            uint4 v1 = ((const uint4*)src)[1];
            uint4 v2 = ((const uint4*)src)[2];
            uint4 v3 = ((const uint4*)src)[3];
            *(uint4*)&Bs[n][kc] = v0;
            *(uint4*)&Bs[n][kc + 8] = v1;
            *(uint4*)&Bs[n][kc + 16] = v2;
            *(uint4*)&Bs[n][kc + 24] = v3;
        }
        __syncthreads();
#pragma unroll
        for (int ks = 0; ks < 4; ks++) {
            int kk = ks * 16 + tig * 2;
            unsigned a0 = *(const unsigned*)&As[wm + grp][kk];
            unsigned a1 = *(const unsigned*)&As[wm + grp + 8][kk];
            unsigned a2 = *(const unsigned*)&As[wm + grp][kk + 8];
            unsigned a3 = *(const unsigned*)&As[wm + grp + 8][kk + 8];
#pragma unroll
            for (int nf = 0; nf < 4; nf++) {
                int n8 = wn + nf * 8 + grp;
                unsigned b0 = *(const unsigned*)&Bs[n8][kk];
                unsigned b1r = *(const unsigned*)&Bs[n8][kk + 8];
                asm volatile(
                    "mma.sync.aligned.m16n8k16.row.col.f32.f16.f16.f32 "
                    "{%0,%1,%2,%3}, {%4,%5,%6,%7}, {%8,%9}, {%0,%1,%2,%3};"
                    : "+f"(acc[nf][0]), "+f"(acc[nf][1]), "+f"(acc[nf][2]), "+f"(acc[nf][3])
                    : "r"(a0), "r"(a1), "r"(a2), "r"(a3), "r"(b0), "r"(b1r));
            }
        }
        __syncthreads();
    }
#pragma unroll
    for (int nf = 0; nf < 4; nf++) {
        int ncol = nblk * 128 + wn + nf * 8 + tig * 2;   // global col 0..255
        float bx_ = 0.f, by_ = 0.f;
        float* obase;
        int oc;
        if (ncol < 128) {
            obase = g_pt; oc = ncol;
            float2 bb = *(const float2*)(b1 + ncol);
            bx_ = bb.x; by_ = bb.y;
        } else {
            obase = g_pb; oc = ncol - 128;
        }
        int n0 = node0 + wm + grp;
        if (n0 < NN)
            *(float2*)(obase + (size_t)n0 * 128 + oc) = make_float2(acc[nf][0] + bx_, acc[nf][1] + by_);
        int n1 = n0 + 8;
        if (n1 < NN)
            *(float2*)(obase + (size_t)n1 * 128 + oc) = make_float2(acc[nf][2] + bx_, acc[nf][3] + by_);
    }
}

// ---------------- kernel 10: per-edge output, CSR order (pb[dst] loaded once/warp) ----------------
__global__ void edge_out_kernel(const float* __restrict__ w2, const float* __restrict__ b2,
                                float* __restrict__ out) {
    GRID_DEP_SYNC();
    int tid = threadIdx.x, w = tid >> 5, lane = tid & 31;
    int node = blockIdx.x * 8 + w;
    int beg = g_rowptr[node], end = g_rowptr[node + 1];
    if (beg == end) return;
    const float4* pt4 = (const float4*)g_pt;
    float4 pbv = ((const float4*)g_pb)[(size_t)node * 32 + lane];
    float4 wv = ((const float4*)w2)[lane];
    float bias = b2[0];
    int k = beg;
    for (; k + 2 <= end; k += 2) {
        int v0 = g_es[k], v1 = g_es[k + 1];
        float4 a0 = pt4[(size_t)ES_S(v0) * 32 + lane];
        float4 a1 = pt4[(size_t)ES_S(v1) * 32 + lane];
        float r0 = fmaxf(a0.x + pbv.x, 0.f) * wv.x + fmaxf(a0.y + pbv.y, 0.f) * wv.y
                 + fmaxf(a0.z + pbv.z, 0.f) * wv.z + fmaxf(a0.w + pbv.w, 0.f) * wv.w;
        float r1 = fmaxf(a1.x + pbv.x, 0.f) * wv.x + fmaxf(a1.y + pbv.y, 0.f) * wv.y
                 + fmaxf(a1.z + pbv.z, 0.f) * wv.z + fmaxf(a1.w + pbv.w, 0.f) * wv.w;
#pragma unroll
        for (int off = 16; off; off >>= 1) {
            r0 += __shfl_down_sync(0xffffffffu, r0, off);
            r1 += __shfl_down_sync(0xffffffffu, r1, off);
        }
        if (lane == 0) {
            out[ES_E(v0)] = 1.f / (1.f + expf(-(r0 + bias)));
            out[ES_E(v1)] = 1.f / (1.f + expf(-(r1 + bias)));
        }
    }
    if (k < end) {
        int v = g_es[k];
        float4 a = pt4[(size_t)ES_S(v) * 32 + lane];
        float r = fmaxf(a.x + pbv.x, 0.f) * wv.x + fmaxf(a.y + pbv.y, 0.f) * wv.y
                + fmaxf(a.z + pbv.z, 0.f) * wv.z + fmaxf(a.w + pbv.w, 0.f) * wv.w;
#pragma unroll
        for (int off = 16; off; off >>= 1) r += __shfl_down_sync(0xffffffffu, r, off);
        if (lane == 0) out[ES_E(v)] = 1.f / (1.f + expf(-(r + bias)));
    }
}

// ---------------- PDL launch helper ----------------
template <typename Kern, typename... Args>
static inline void launch_pdl(Kern kernel, dim3 grid, dim3 block, Args... args) {
    cudaLaunchConfig_t cfg = {};
    cfg.gridDim = grid;
    cfg.blockDim = block;
    cfg.dynamicSmemBytes = 0;
    cfg.stream = 0;
    cudaLaunchAttribute attr[1];
    attr[0].id = cudaLaunchAttributeProgrammaticStreamSerialization;
    attr[0].val.programmaticStreamSerializationAllowed = 1;
    cfg.attrs = attr;
    cfg.numAttrs = 1;
    cudaLaunchKernelEx(&cfg, kernel, args...);
}

// ---------------- launch ----------------
extern "C" void kernel_launch(void* const* d_in, const int* in_sizes, int n_in,
                              void* d_out, int out_size) {
    int off, iE, iT;
    if (in_sizes[0] == 2 * EE) { off = 2; iE = 0; iT = 1; }
    else                       { off = 0; iE = 24; iT = 25; }
    const int* ei = (const int*)d_in[iE];
    const int* et = (const int*)d_in[iT];
    const int* src = ei;
    const int* dst = ei + EE;
    const float* basis0 = (const float*)d_in[off + 0];
    const float* comp0  = (const float*)d_in[off + 1];
    const float* root0  = (const float*)d_in[off + 2];
    const float* rbias0 = (const float*)d_in[off + 3];
    const float* basis1 = (const float*)d_in[off + 4];
    const float* comp1  = (const float*)d_in[off + 5];
    const float* root1  = (const float*)d_in[off + 6];
    const float* rbias1 = (const float*)d_in[off + 7];
    const float* basis2 = (const float*)d_in[off + 8];
    const float* comp2  = (const float*)d_in[off + 9];
    const float* root2  = (const float*)d_in[off + 10];
    const float* rbias2 = (const float*)d_in[off + 11];
    const float* basis3 = (const float*)d_in[off + 12];
    const float* comp3  = (const float*)d_in[off + 13];
    const float* root3  = (const float*)d_in[off + 14];
    const float* rbias3 = (const float*)d_in[off + 15];
    const float* gw  = (const float*)d_in[off + 16];
    const float* gas = (const float*)d_in[off + 17];
    const float* gad = (const float*)d_in[off + 18];
    const float* gb  = (const float*)d_in[off + 19];
    const float* w1  = (const float*)d_in[off + 20];
    const float* b1  = (const float*)d_in[off + 21];
    const float* w2  = (const float*)d_in[off + 22];
    const float* b2  = (const float*)d_in[off + 23];
    float* out = (float*)d_out;

    launch_pdl(pre_count_kernel, dim3(PRE_BLOCKS + CNT_BLOCKS + W1H_BLOCKS), dim3(256),
               basis0, comp0, basis1, comp1, basis2, comp2, basis3, comp3, dst, w1);
    launch_pdl(scan_kernel, dim3(1), dim3(1024));
    launch_pdl(scatter_kernel, dim3(CNT_BLOCKS), dim3(256), src, dst, et);

    launch_pdl(l0d1_kernel, dim3(NN / 8), dim3(256), root0, rbias0, root1, rbias1);
    launch_pdl(a1d2_kernel, dim3(NN / 8), dim3(256), root2, rbias2);
    launch_pdl(a2d3_kernel, dim3(NN / 8), dim3(256), root3, rbias3);

    launch_pdl(agg3_gath_kernel, dim3(NN / 16), dim3(512), gw, gas, gad);
    launch_pdl(gatagg_kernel, dim3(NN / 16), dim3(256), gb);
    launch_pdl(ptpb_mma_kernel, dim3((NN + MT - 1) / MT, 2), dim3(256), b1);
    launch_pdl(edge_out_kernel, dim3(NN / 8), dim3(256), w2, b2, out);
}